// round 1
// baseline (speedup 1.0000x reference)
#include <cuda_runtime.h>
#include <math.h>
#include <float.h>

// ---------------- problem constants ----------------
#define BB   8
#define NN   515
#define DD   1024
#define HH   8
#define DHE  64
#define LL   4
#define FFD  4096
#define NKV  516              // N + 1 (null kv prepended)
#define MM   (BB*NN)          // 4120 tokens
#define EPSL 1e-5f

// ---------------- scratch (static device globals; no allocs allowed) ------
__device__ float g_X  [MM*DD];        // residual stream
__device__ float g_XN [MM*DD];        // layernorm output
__device__ float g_Q  [MM*512];       // q  (m, h*64+d)
__device__ float g_KV [MM*128];       // raw kv projection
__device__ float g_K  [BB*NKV*DHE];   // normalized k incl. null
__device__ float g_V  [BB*NKV*DHE];   // v incl. null
__device__ float g_O  [MM*512];       // attention output
__device__ float g_T  [MM*DD];        // gemm temp
__device__ float g_Hb [MM*2*FFD];     // ff hidden (a|g)
__device__ float g_AG [MM*FFD];       // a * silu(g)
__device__ float g_bias[HH*NN*NKV];   // rel-pos bias [h][i][j]
__device__ float g_cos[NN*16];
__device__ float g_sin[NN*16];

// ---------------- reductions ----------------
__device__ __forceinline__ float warpReduceSum(float v) {
    #pragma unroll
    for (int o = 16; o > 0; o >>= 1) v += __shfl_xor_sync(0xffffffffu, v, o);
    return v;
}
__device__ __forceinline__ float warpReduceMax(float v) {
    #pragma unroll
    for (int o = 16; o > 0; o >>= 1) v = fmaxf(v, __shfl_xor_sync(0xffffffffu, v, o));
    return v;
}
__device__ __forceinline__ float blockReduceSum(float v) {
    __shared__ float sh[8];
    int lane = threadIdx.x & 31, w = threadIdx.x >> 5;
    v = warpReduceSum(v);
    __syncthreads();
    if (lane == 0) sh[w] = v;
    __syncthreads();
    if (w == 0) {
        float t = (lane < 8) ? sh[lane] : 0.f;
        t = warpReduceSum(t);
        if (lane == 0) sh[0] = t;
    }
    __syncthreads();
    return sh[0];
}
__device__ __forceinline__ float blockReduceMax(float v) {
    __shared__ float sh[8];
    int lane = threadIdx.x & 31, w = threadIdx.x >> 5;
    v = warpReduceMax(v);
    __syncthreads();
    if (lane == 0) sh[w] = v;
    __syncthreads();
    if (w == 0) {
        float t = (lane < 8) ? sh[lane] : -FLT_MAX;
        t = warpReduceMax(t);
        if (lane == 0) sh[0] = t;
    }
    __syncthreads();
    return sh[0];
}

// ---------------- SGEMM: C[M,N] = A[M,K] @ B[K,N] (+bias) (+=) -----------
// 128x128 tile, BK=8, 8x8 per thread, 256 threads.
#define BM 128
#define BN 128
#define BK 8
#define TM 8
#define TN 8

__global__ __launch_bounds__(256)
void sgemm_kernel(const float* __restrict__ A, const float* __restrict__ B,
                  const float* __restrict__ bias, float* __restrict__ C,
                  int M, int N, int K, int accumulate)
{
    __shared__ float As[BK][BM];
    __shared__ float Bs[BK][BN];
    const int tid = threadIdx.x;
    const int block_row = blockIdx.y * BM;
    const int block_col = blockIdx.x * BN;
    const int trow = (tid >> 4) * TM;   // 16 thread-rows
    const int tcol = (tid & 15) * TN;   // 16 thread-cols

    float acc[TM][TN];
    #pragma unroll
    for (int i = 0; i < TM; i++)
        #pragma unroll
        for (int j = 0; j < TN; j++) acc[i][j] = 0.f;

    const int aRow = tid >> 3;   // 0..31
    const int aCol = tid & 7;
    const int bRow = tid >> 7;   // 0..1
    const int bCol = tid & 127;

    for (int k0 = 0; k0 < K; k0 += BK) {
        #pragma unroll
        for (int i = 0; i < 4; i++) {
            int r  = aRow + i * 32;
            int gr = block_row + r;
            As[aCol][r] = (gr < M) ? A[(size_t)gr * K + k0 + aCol] : 0.f;
        }
        #pragma unroll
        for (int i = 0; i < 4; i++) {
            int r = bRow + i * 2;
            Bs[r][bCol] = B[(size_t)(k0 + r) * N + block_col + bCol];
        }
        __syncthreads();
        #pragma unroll
        for (int k = 0; k < BK; k++) {
            float4 a0 = *(const float4*)&As[k][trow];
            float4 a1 = *(const float4*)&As[k][trow + 4];
            float4 b0 = *(const float4*)&Bs[k][tcol];
            float4 b1 = *(const float4*)&Bs[k][tcol + 4];
            float a[TM] = {a0.x,a0.y,a0.z,a0.w,a1.x,a1.y,a1.z,a1.w};
            float b[TN] = {b0.x,b0.y,b0.z,b0.w,b1.x,b1.y,b1.z,b1.w};
            #pragma unroll
            for (int i = 0; i < TM; i++)
                #pragma unroll
                for (int j = 0; j < TN; j++)
                    acc[i][j] = fmaf(a[i], b[j], acc[i][j]);
        }
        __syncthreads();
    }

    #pragma unroll
    for (int i = 0; i < TM; i++) {
        int gr = block_row + trow + i;
        if (gr >= M) continue;
        float* cp = C + (size_t)gr * N + block_col + tcol;
        #pragma unroll
        for (int j = 0; j < TN; j++) {
            float v = acc[i][j];
            if (bias) v += bias[block_col + tcol + j];
            if (accumulate) cp[j] += v; else cp[j] = v;
        }
    }
}

// ---------------- LayerNorm (mode 0: out = LN*g, 1: out += LN*g, 2: stable)
__global__ __launch_bounds__(256)
void ln_kernel(const float* __restrict__ in, const float* __restrict__ g,
               float* __restrict__ out, int mode)
{
    const int row = blockIdx.x;
    const float* xr = in + (size_t)row * DD;
    const int t = threadIdx.x;
    float v[4];
    #pragma unroll
    for (int i = 0; i < 4; i++) v[i] = xr[t + i * 256];

    if (mode == 2) {
        float lm = -FLT_MAX;
        #pragma unroll
        for (int i = 0; i < 4; i++) lm = fmaxf(lm, v[i]);
        float mx = blockReduceMax(lm);
        float inv = 1.f / mx;
        #pragma unroll
        for (int i = 0; i < 4; i++) v[i] *= inv;
    }
    float s = 0.f;
    #pragma unroll
    for (int i = 0; i < 4; i++) s += v[i];
    float mean = blockReduceSum(s) * (1.f / DD);
    float vs = 0.f;
    #pragma unroll
    for (int i = 0; i < 4; i++) { float d = v[i] - mean; vs += d * d; }
    float var  = blockReduceSum(vs) * (1.f / DD);
    float rstd = rsqrtf(var + EPSL);
    #pragma unroll
    for (int i = 0; i < 4; i++) {
        int c = t + i * 256;
        float y = (v[i] - mean) * rstd * g[c];
        if (mode == 1) out[(size_t)row * DD + c] += y;
        else           out[(size_t)row * DD + c]  = y;
    }
}

// ---------------- precompute: rotary tables + rel-pos bias ---------------
__global__ void rope_kernel() {
    int idx = blockIdx.x * blockDim.x + threadIdx.x;
    if (idx >= NN * 16) return;
    int p = idx >> 4, i = idx & 15;
    float inv = powf(10000.f, -(float)(2 * i) / 32.f);
    float fr  = (float)p * inv;
    g_cos[idx] = cosf(fr);
    g_sin[idx] = sinf(fr);
}

__global__ void bias_kernel(const float* __restrict__ emb) {
    int idx = blockIdx.x * blockDim.x + threadIdx.x;
    if (idx >= NN * NKV) return;
    int i = idx / NKV, j = idx % NKV;
    int nn = max(i - j, 0);
    int bucket;
    if (nn < 16) bucket = nn;
    else {
        float nf = (float)nn;
        int vl = 16 + (int)(logf(nf * (1.f / 16.f)) / logf(8.f) * 16.f);
        bucket = min(vl, 31);
    }
    #pragma unroll
    for (int h = 0; h < HH; h++)
        g_bias[((size_t)h * NN + i) * NKV + j] = emb[bucket * HH + h];
}

// ---------------- q post: rotary + l2norm * 4 ----------------------------
__global__ __launch_bounds__(256)
void qpost_kernel() {
    int gw   = (blockIdx.x * blockDim.x + threadIdx.x) >> 5;
    int lane = threadIdx.x & 31;
    if (gw >= MM * HH) return;
    int m = gw / HH, h = gw % HH;
    int pos = m % NN;
    float* qp = g_Q + (size_t)m * 512 + h * 64;
    float q0 = qp[lane], q1 = qp[lane + 32];
    float c = g_cos[pos * 16 + (lane >> 1)];
    float s = g_sin[pos * 16 + (lane >> 1)];
    float part = __shfl_xor_sync(0xffffffffu, q0, 1);
    q0 = (lane & 1) ? fmaf(q0, c, part * s) : fmaf(q0, c, -part * s);
    float nrm = warpReduceSum(q0 * q0 + q1 * q1);
    float inv = 4.f * rsqrtf(nrm);   // sqrt(SCALE)=4 ; l2norm cancels the *16
    qp[lane] = q0 * inv;
    qp[lane + 32] = q1 * inv;
}

// ---------------- kv post: rotary on k, prepend null kv, l2norm(k)*4 -----
__global__ __launch_bounds__(256)
void kvpost_kernel(const float* __restrict__ nullkv) {
    int gw   = (blockIdx.x * blockDim.x + threadIdx.x) >> 5;
    int lane = threadIdx.x & 31;
    if (gw >= BB * NKV) return;
    int b = gw / NKV, j = gw % NKV;
    float k0, k1, v0, v1;
    if (j == 0) {
        k0 = nullkv[lane];      k1 = nullkv[lane + 32];
        v0 = nullkv[64 + lane]; v1 = nullkv[96 + lane];
    } else {
        int pos = j - 1;
        const float* kv = g_KV + ((size_t)(b * NN + pos)) * 128;
        k0 = kv[lane];      k1 = kv[lane + 32];
        v0 = kv[64 + lane]; v1 = kv[96 + lane];
        float c = g_cos[pos * 16 + (lane >> 1)];
        float s = g_sin[pos * 16 + (lane >> 1)];
        float part = __shfl_xor_sync(0xffffffffu, k0, 1);
        k0 = (lane & 1) ? fmaf(k0, c, part * s) : fmaf(k0, c, -part * s);
    }
    float nrm = warpReduceSum(k0 * k0 + k1 * k1);
    float inv = 4.f * rsqrtf(nrm);
    size_t o = ((size_t)(b * NKV + j)) * 64;
    g_K[o + lane] = k0 * inv;  g_K[o + lane + 32] = k1 * inv;
    g_V[o + lane] = v0;        g_V[o + lane + 32] = v1;
}

// ---------------- attention: one warp per (b,h,i), online softmax --------
__global__ __launch_bounds__(256)
void attn_kernel() {
    int gw   = (blockIdx.x * blockDim.x + threadIdx.x) >> 5;
    int lane = threadIdx.x & 31;
    if (gw >= BB * HH * NN) return;
    int i  = gw % NN;
    int bh = gw / NN;
    int h  = bh % HH, b = bh / HH;

    const float* qp = g_Q + ((size_t)(b * NN + i)) * 512 + h * 64;
    float q0 = qp[lane], q1 = qp[lane + 32];
    const float* Kb = g_K + (size_t)b * NKV * 64;
    const float* Vb = g_V + (size_t)b * NKV * 64;
    const float* bp = g_bias + ((size_t)h * NN + i) * NKV;

    float m = -1e30f, lsum = 0.f, o0 = 0.f, o1 = 0.f;
    int jmax = i + 1;                 // causal: j <= i+1 (j=0 is null kv)
    for (int j = 0; j <= jmax; j++) {
        const float* kp = Kb + (size_t)j * 64;
        float d = q0 * kp[lane] + q1 * kp[lane + 32];
        #pragma unroll
        for (int off = 16; off > 0; off >>= 1)
            d += __shfl_xor_sync(0xffffffffu, d, off);
        float s  = d + bp[j];
        float mn = fmaxf(m, s);
        float corr = __expf(m - mn);
        float w    = __expf(s - mn);
        lsum = lsum * corr + w;
        o0 = o0 * corr + w * Vb[(size_t)j * 64 + lane];
        o1 = o1 * corr + w * Vb[(size_t)j * 64 + lane + 32];
        m = mn;
    }
    float inv = 1.f / lsum;
    float* op = g_O + ((size_t)(b * NN + i)) * 512 + h * 64;
    op[lane] = o0 * inv;
    op[lane + 32] = o1 * inv;
}

// ---------------- GLU: ag = a * silu(g) ----------------------------------
__global__ void glu_kernel() {
    int idx = blockIdx.x * blockDim.x + threadIdx.x;
    if (idx >= MM * FFD) return;
    int r = idx / FFD, c = idx % FFD;
    float a = g_Hb[(size_t)r * 2 * FFD + c];
    float g = g_Hb[(size_t)r * 2 * FFD + FFD + c];
    g_AG[idx] = a * g / (1.f + expf(-g));
}

// ---------------- copy -----------------------------------------------------
__global__ void copy_kernel(const float* __restrict__ src, float* __restrict__ dst, int n) {
    int idx = blockIdx.x * blockDim.x + threadIdx.x;
    if (idx < n) dst[idx] = src[idx];
}

// ---------------- host orchestration --------------------------------------
static inline void run_gemm(const float* A, const float* B, const float* bias,
                            float* C, int M, int N, int K, int acc) {
    dim3 grid(N / BN, (M + BM - 1) / BM);
    sgemm_kernel<<<grid, 256>>>(A, B, bias, C, M, N, K, acc);
}

extern "C" void kernel_launch(void* const* d_in, const int* in_sizes, int n_in,
                              void* d_out, int out_size) {
    (void)in_sizes; (void)n_in; (void)out_size;
    const float* x            = (const float*)d_in[0];
    const float* attn_norm_g  = (const float*)d_in[1];
    const float* Wq           = (const float*)d_in[2];
    const float* Wkv          = (const float*)d_in[3];
    const float* bkv          = (const float*)d_in[4];
    const float* null_kv      = (const float*)d_in[5];
    const float* Wo           = (const float*)d_in[6];
    const float* out_norm_g   = (const float*)d_in[7];
    const float* ff_norm_g    = (const float*)d_in[8];
    const float* Wff1         = (const float*)d_in[9];
    const float* Wff2         = (const float*)d_in[10];
    const float* relpos       = (const float*)d_in[11];
    const float* final_norm_g = (const float*)d_in[12];
    const float* Wproj        = (const float*)d_in[13];
    float* out = (float*)d_out;

    float *X, *XN, *Q, *KV, *T, *O, *Hb, *AG;
    cudaGetSymbolAddress((void**)&X,  g_X);
    cudaGetSymbolAddress((void**)&XN, g_XN);
    cudaGetSymbolAddress((void**)&Q,  g_Q);
    cudaGetSymbolAddress((void**)&KV, g_KV);
    cudaGetSymbolAddress((void**)&T,  g_T);
    cudaGetSymbolAddress((void**)&O,  g_O);
    cudaGetSymbolAddress((void**)&Hb, g_Hb);
    cudaGetSymbolAddress((void**)&AG, g_AG);

    copy_kernel<<<(MM * DD + 255) / 256, 256>>>(x, X, MM * DD);
    rope_kernel<<<(NN * 16 + 255) / 256, 256>>>();
    bias_kernel<<<(NN * NKV + 255) / 256, 256>>>(relpos);

    for (int l = 0; l < LL; l++) {
        // attention block
        ln_kernel<<<MM, 256>>>(X, attn_norm_g + (size_t)l * DD, XN, 0);
        run_gemm(XN, Wq  + (size_t)l * DD * 512, nullptr,          Q,  MM, 512, DD, 0);
        run_gemm(XN, Wkv + (size_t)l * DD * 128, bkv + l * 128,    KV, MM, 128, DD, 0);
        qpost_kernel<<<(MM * HH * 32 + 255) / 256, 256>>>();
        kvpost_kernel<<<(BB * NKV * 32 + 255) / 256, 256>>>(null_kv + (size_t)l * 128);
        attn_kernel<<<(BB * HH * NN * 32 + 255) / 256, 256>>>();
        run_gemm(O, Wo + (size_t)l * 512 * DD, nullptr, T, MM, DD, 512, 0);
        ln_kernel<<<MM, 256>>>(T, out_norm_g + (size_t)l * DD, X, 1);   // x += LN(...)
        // ff block
        ln_kernel<<<MM, 256>>>(X, ff_norm_g + (size_t)l * DD, XN, 0);
        run_gemm(XN, Wff1 + (size_t)l * DD * 2 * FFD, nullptr, Hb, MM, 2 * FFD, DD, 0);
        glu_kernel<<<(MM * FFD + 255) / 256, 256>>>();
        run_gemm(AG, Wff2 + (size_t)l * FFD * DD, nullptr, X, MM, DD, FFD, 1); // x += ...
    }

    ln_kernel<<<MM, 256>>>(X, final_norm_g, XN, 2);   // stable LN
    run_gemm(XN, Wproj, nullptr, out, MM, DD, DD, 0);
}

// round 3
// speedup vs baseline: 2.3322x; 2.3322x over previous
#include <cuda_runtime.h>
#include <cuda_bf16.h>
#include <math.h>
#include <float.h>
#include <stdint.h>

// ---------------- problem constants ----------------
#define BB   8
#define NN   515
#define DD   1024
#define HH   8
#define DHE  64
#define LL   4
#define FFD  4096
#define NKV  516              // N + 1 (null kv prepended)
#define MM   (BB*NN)          // 4120 tokens
#define EPSL 1e-5f

// ---------------- scratch (static device globals; no allocs allowed) ------
__device__ float g_X  [MM*DD];
__device__ float g_XN [MM*DD];
__device__ float g_Q  [MM*512];
__device__ float g_KV [MM*128];
__device__ float g_K  [BB*NKV*DHE];
__device__ float g_V  [BB*NKV*DHE];
__device__ float g_O  [MM*512];
__device__ float g_T  [MM*DD];
__device__ float g_Hb [MM*2*FFD];
__device__ float g_AG [MM*FFD];
__device__ float g_bias[HH*NN*NKV];
__device__ float g_cos[NN*16];
__device__ float g_sin[NN*16];

// ---------------- reductions ----------------
__device__ __forceinline__ float warpReduceSum(float v) {
    #pragma unroll
    for (int o = 16; o > 0; o >>= 1) v += __shfl_xor_sync(0xffffffffu, v, o);
    return v;
}
__device__ __forceinline__ float warpReduceMax(float v) {
    #pragma unroll
    for (int o = 16; o > 0; o >>= 1) v = fmaxf(v, __shfl_xor_sync(0xffffffffu, v, o));
    return v;
}
__device__ __forceinline__ float blockReduceSum(float v) {
    __shared__ float sh[8];
    int lane = threadIdx.x & 31, w = threadIdx.x >> 5;
    v = warpReduceSum(v);
    __syncthreads();
    if (lane == 0) sh[w] = v;
    __syncthreads();
    if (w == 0) {
        float t = (lane < 8) ? sh[lane] : 0.f;
        t = warpReduceSum(t);
        if (lane == 0) sh[0] = t;
    }
    __syncthreads();
    return sh[0];
}
__device__ __forceinline__ float blockReduceMax(float v) {
    __shared__ float sh[8];
    int lane = threadIdx.x & 31, w = threadIdx.x >> 5;
    v = warpReduceMax(v);
    __syncthreads();
    if (lane == 0) sh[w] = v;
    __syncthreads();
    if (w == 0) {
        float t = (lane < 8) ? sh[lane] : -FLT_MAX;
        t = warpReduceMax(t);
        if (lane == 0) sh[0] = t;
    }
    __syncthreads();
    return sh[0];
}

// ================= split-bf16 tensor-core GEMM =============================
// C[M,N] = A[M,K] @ B[K,N] (+bias) (+=), fp32 in/out.
// Each fp32 x split as x = hi + lo (both bf16). D += Ah*Bh + Ah*Bl + Al*Bh
// with mma.sync.m16n8k16.bf16, fp32 accum. Per-product err ~1e-5.
// CTA tile 128x128, GBK=32 floats (16 k-pairs), 8 warps, warp tile 64x32.
// Register double-buffering of global loads.
#define GBM 128
#define GBN 128
#define GBK 32
#define ASTR 136
#define BSTR 136

__device__ __forceinline__ uint32_t pack_hi(float x, float y, float& rx, float& ry) {
    __nv_bfloat162 h = __floats2bfloat162_rn(x, y);
    rx = x - __bfloat162float(h.x);
    ry = y - __bfloat162float(h.y);
    return *(uint32_t*)&h;
}
__device__ __forceinline__ uint32_t pack_bf(float x, float y) {
    __nv_bfloat162 h = __floats2bfloat162_rn(x, y);
    return *(uint32_t*)&h;
}
__device__ __forceinline__ void mma_bf16(float* c, const uint32_t* a, const uint32_t* b) {
    asm volatile(
        "mma.sync.aligned.m16n8k16.row.col.f32.bf16.bf16.f32 "
        "{%0,%1,%2,%3}, {%4,%5,%6,%7}, {%8,%9}, {%0,%1,%2,%3};"
        : "+f"(c[0]), "+f"(c[1]), "+f"(c[2]), "+f"(c[3])
        : "r"(a[0]), "r"(a[1]), "r"(a[2]), "r"(a[3]), "r"(b[0]), "r"(b[1]));
}

__global__ __launch_bounds__(256)
void bgemm_kernel(const float* __restrict__ A, const float* __restrict__ B,
                  const float* __restrict__ bias, float* __restrict__ C,
                  int M, int N, int K, int accumulate)
{
    __shared__ uint32_t Ah[16][ASTR], Al[16][ASTR];
    __shared__ uint32_t Bh[16][BSTR], Bl[16][BSTR];

    const int tid  = threadIdx.x;
    const int lane = tid & 31;
    const int warp = tid >> 5;
    const int gid  = lane >> 2;
    const int tig  = lane & 3;
    const int warp_row = (warp & 1) * 64;
    const int warp_col = (warp >> 1) * 32;
    const int block_row = blockIdx.y * GBM;
    const int block_col = blockIdx.x * GBN;

    // ---- loader index precompute
    int aRow[4], aK2[4];
    #pragma unroll
    for (int i = 0; i < 4; i++) {
        int idx = tid + i * 256;        // 1024 float4 units (128 rows x 8)
        aRow[i] = idx >> 3;
        aK2[i]  = (idx & 7) * 2;        // pair index (even)
    }
    int bKp[2], bNq[2];
    #pragma unroll
    for (int p = 0; p < 2; p++) {
        int u = tid + p * 256;          // 512 units (16 kp x 32 nq)
        bKp[p] = u >> 5;
        bNq[p] = u & 31;
    }

    float4 aP[4];
    float4 bP[2][2];

    // prefetch chunk 0
    #pragma unroll
    for (int i = 0; i < 4; i++) {
        int gr = block_row + aRow[i];
        aP[i] = (gr < M) ? *(const float4*)&A[(size_t)gr * K + aK2[i] * 2]
                         : make_float4(0.f, 0.f, 0.f, 0.f);
    }
    #pragma unroll
    for (int p = 0; p < 2; p++) {
        const float* bp = &B[(size_t)(2 * bKp[p]) * N + block_col + bNq[p] * 4];
        bP[p][0] = *(const float4*)bp;
        bP[p][1] = *(const float4*)(bp + N);
    }

    float acc[4][4][4];
    #pragma unroll
    for (int a = 0; a < 4; a++)
        #pragma unroll
        for (int b = 0; b < 4; b++)
            #pragma unroll
            for (int c = 0; c < 4; c++) acc[a][b][c] = 0.f;

    for (int k0 = 0; k0 < K; k0 += GBK) {
        __syncthreads();
        // ---- convert prefetched regs -> split bf16 smem
        #pragma unroll
        for (int i = 0; i < 4; i++) {
            float rx, ry, rz, rw;
            uint32_t h0 = pack_hi(aP[i].x, aP[i].y, rx, ry);
            uint32_t h1 = pack_hi(aP[i].z, aP[i].w, rz, rw);
            Ah[aK2[i]    ][aRow[i]] = h0;
            Ah[aK2[i] + 1][aRow[i]] = h1;
            Al[aK2[i]    ][aRow[i]] = pack_bf(rx, ry);
            Al[aK2[i] + 1][aRow[i]] = pack_bf(rz, rw);
        }
        #pragma unroll
        for (int p = 0; p < 2; p++) {
            uint32_t h[4], l[4];
            const float* u = (const float*)&bP[p][0];
            const float* w = (const float*)&bP[p][1];
            #pragma unroll
            for (int j = 0; j < 4; j++) {
                float rx, ry;
                h[j] = pack_hi(u[j], w[j], rx, ry);
                l[j] = pack_bf(rx, ry);
            }
            *(uint4*)&Bh[bKp[p]][bNq[p] * 4] = make_uint4(h[0], h[1], h[2], h[3]);
            *(uint4*)&Bl[bKp[p]][bNq[p] * 4] = make_uint4(l[0], l[1], l[2], l[3]);
        }
        __syncthreads();

        // ---- prefetch next chunk
        if (k0 + GBK < K) {
            #pragma unroll
            for (int i = 0; i < 4; i++) {
                int gr = block_row + aRow[i];
                aP[i] = (gr < M) ? *(const float4*)&A[(size_t)gr * K + k0 + GBK + aK2[i] * 2]
                                 : make_float4(0.f, 0.f, 0.f, 0.f);
            }
            #pragma unroll
            for (int p = 0; p < 2; p++) {
                const float* bp = &B[(size_t)(k0 + GBK + 2 * bKp[p]) * N + block_col + bNq[p] * 4];
                bP[p][0] = *(const float4*)bp;
                bP[p][1] = *(const float4*)(bp + N);
            }
        }

        // ---- compute: two k16 steps
        #pragma unroll
        for (int kk2 = 0; kk2 < 16; kk2 += 8) {
            uint32_t ah[4][4], al[4][4], bh[4][2], bl[4][2];
            #pragma unroll
            for (int mt = 0; mt < 4; mt++) {
                int m0 = warp_row + mt * 16 + gid;
                ah[mt][0] = Ah[kk2 + tig    ][m0    ];
                ah[mt][1] = Ah[kk2 + tig    ][m0 + 8];
                ah[mt][2] = Ah[kk2 + tig + 4][m0    ];
                ah[mt][3] = Ah[kk2 + tig + 4][m0 + 8];
                al[mt][0] = Al[kk2 + tig    ][m0    ];
                al[mt][1] = Al[kk2 + tig    ][m0 + 8];
                al[mt][2] = Al[kk2 + tig + 4][m0    ];
                al[mt][3] = Al[kk2 + tig + 4][m0 + 8];
            }
            #pragma unroll
            for (int nt = 0; nt < 4; nt++) {
                int n0 = warp_col + nt * 8 + gid;
                bh[nt][0] = Bh[kk2 + tig    ][n0];
                bh[nt][1] = Bh[kk2 + tig + 4][n0];
                bl[nt][0] = Bl[kk2 + tig    ][n0];
                bl[nt][1] = Bl[kk2 + tig + 4][n0];
            }
            #pragma unroll
            for (int mt = 0; mt < 4; mt++)
                #pragma unroll
                for (int nt = 0; nt < 4; nt++) {
                    mma_bf16(acc[mt][nt], ah[mt], bh[nt]);
                    mma_bf16(acc[mt][nt], ah[mt], bl[nt]);
                    mma_bf16(acc[mt][nt], al[mt], bh[nt]);
                }
        }
    }

    // ---- epilogue
    #pragma unroll
    for (int mt = 0; mt < 4; mt++) {
        int r0 = block_row + warp_row + mt * 16 + gid;
        #pragma unroll
        for (int half = 0; half < 2; half++) {
            int r = r0 + half * 8;
            if (r >= M) continue;
            #pragma unroll
            for (int nt = 0; nt < 4; nt++) {
                int col = block_col + warp_col + nt * 8 + 2 * tig;
                float v0 = acc[mt][nt][half * 2 + 0];
                float v1 = acc[mt][nt][half * 2 + 1];
                if (bias) { v0 += bias[col]; v1 += bias[col + 1]; }
                float* cp = C + (size_t)r * N + col;
                if (accumulate) { cp[0] += v0; cp[1] += v1; }
                else            { cp[0]  = v0; cp[1]  = v1; }
            }
        }
    }
}

// ---------------- LayerNorm (mode 0: out = LN*g, 1: out += LN*g, 2: stable)
__global__ __launch_bounds__(256)
void ln_kernel(const float* __restrict__ in, const float* __restrict__ g,
               float* __restrict__ out, int mode)
{
    const int row = blockIdx.x;
    const float* xr = in + (size_t)row * DD;
    const int t = threadIdx.x;
    float v[4];
    #pragma unroll
    for (int i = 0; i < 4; i++) v[i] = xr[t + i * 256];

    if (mode == 2) {
        float lm = -FLT_MAX;
        #pragma unroll
        for (int i = 0; i < 4; i++) lm = fmaxf(lm, v[i]);
        float mx = blockReduceMax(lm);
        float inv = 1.f / mx;
        #pragma unroll
        for (int i = 0; i < 4; i++) v[i] *= inv;
    }
    float s = 0.f;
    #pragma unroll
    for (int i = 0; i < 4; i++) s += v[i];
    float mean = blockReduceSum(s) * (1.f / DD);
    float vs = 0.f;
    #pragma unroll
    for (int i = 0; i < 4; i++) { float d = v[i] - mean; vs += d * d; }
    float var  = blockReduceSum(vs) * (1.f / DD);
    float rstd = rsqrtf(var + EPSL);
    #pragma unroll
    for (int i = 0; i < 4; i++) {
        int c = t + i * 256;
        float y = (v[i] - mean) * rstd * g[c];
        if (mode == 1) out[(size_t)row * DD + c] += y;
        else           out[(size_t)row * DD + c]  = y;
    }
}

// ---------------- precompute: rotary tables + rel-pos bias ---------------
__global__ void rope_kernel() {
    int idx = blockIdx.x * blockDim.x + threadIdx.x;
    if (idx >= NN * 16) return;
    int p = idx >> 4, i = idx & 15;
    float inv = powf(10000.f, -(float)(2 * i) / 32.f);
    float fr  = (float)p * inv;
    g_cos[idx] = cosf(fr);
    g_sin[idx] = sinf(fr);
}

__global__ void bias_kernel(const float* __restrict__ emb) {
    int idx = blockIdx.x * blockDim.x + threadIdx.x;
    if (idx >= NN * NKV) return;
    int i = idx / NKV, j = idx % NKV;
    int nn = max(i - j, 0);
    int bucket;
    if (nn < 16) bucket = nn;
    else {
        float nf = (float)nn;
        int vl = 16 + (int)(logf(nf * (1.f / 16.f)) / logf(8.f) * 16.f);
        bucket = min(vl, 31);
    }
    #pragma unroll
    for (int h = 0; h < HH; h++)
        g_bias[((size_t)h * NN + i) * NKV + j] = emb[bucket * HH + h];
}

// ---------------- q post: rotary + l2norm * 4 ----------------------------
__global__ __launch_bounds__(256)
void qpost_kernel() {
    int gw   = (blockIdx.x * blockDim.x + threadIdx.x) >> 5;
    int lane = threadIdx.x & 31;
    if (gw >= MM * HH) return;
    int m = gw / HH, h = gw % HH;
    int pos = m % NN;
    float* qp = g_Q + (size_t)m * 512 + h * 64;
    float q0 = qp[lane], q1 = qp[lane + 32];
    float c = g_cos[pos * 16 + (lane >> 1)];
    float s = g_sin[pos * 16 + (lane >> 1)];
    float part = __shfl_xor_sync(0xffffffffu, q0, 1);
    q0 = (lane & 1) ? fmaf(q0, c, part * s) : fmaf(q0, c, -part * s);
    float nrm = warpReduceSum(q0 * q0 + q1 * q1);
    float inv = 4.f * rsqrtf(nrm);
    qp[lane] = q0 * inv;
    qp[lane + 32] = q1 * inv;
}

// ---------------- kv post: rotary on k, prepend null kv, l2norm(k)*4 -----
__global__ __launch_bounds__(256)
void kvpost_kernel(const float* __restrict__ nullkv) {
    int gw   = (blockIdx.x * blockDim.x + threadIdx.x) >> 5;
    int lane = threadIdx.x & 31;
    if (gw >= BB * NKV) return;
    int b = gw / NKV, j = gw % NKV;
    float k0, k1, v0, v1;
    if (j == 0) {
        k0 = nullkv[lane];      k1 = nullkv[lane + 32];
        v0 = nullkv[64 + lane]; v1 = nullkv[96 + lane];
    } else {
        int pos = j - 1;
        const float* kv = g_KV + ((size_t)(b * NN + pos)) * 128;
        k0 = kv[lane];      k1 = kv[lane + 32];
        v0 = kv[64 + lane]; v1 = kv[96 + lane];
        float c = g_cos[pos * 16 + (lane >> 1)];
        float s = g_sin[pos * 16 + (lane >> 1)];
        float part = __shfl_xor_sync(0xffffffffu, k0, 1);
        k0 = (lane & 1) ? fmaf(k0, c, part * s) : fmaf(k0, c, -part * s);
    }
    float nrm = warpReduceSum(k0 * k0 + k1 * k1);
    float inv = 4.f * rsqrtf(nrm);
    size_t o = ((size_t)(b * NKV + j)) * 64;
    g_K[o + lane] = k0 * inv;  g_K[o + lane + 32] = k1 * inv;
    g_V[o + lane] = v0;        g_V[o + lane + 32] = v1;
}

// ---------------- attention: one warp per (b,h,i), online softmax --------
__global__ __launch_bounds__(256)
void attn_kernel() {
    int gw   = (blockIdx.x * blockDim.x + threadIdx.x) >> 5;
    int lane = threadIdx.x & 31;
    if (gw >= BB * HH * NN) return;
    int i  = gw % NN;
    int bh = gw / NN;
    int h  = bh % HH, b = bh / HH;

    const float* qp = g_Q + ((size_t)(b * NN + i)) * 512 + h * 64;
    float q0 = qp[lane], q1 = qp[lane + 32];
    const float* Kb = g_K + (size_t)b * NKV * 64;
    const float* Vb = g_V + (size_t)b * NKV * 64;
    const float* bp = g_bias + ((size_t)h * NN + i) * NKV;

    float m = -1e30f, lsum = 0.f, o0 = 0.f, o1 = 0.f;
    int jmax = i + 1;
    for (int j = 0; j <= jmax; j++) {
        const float* kp = Kb + (size_t)j * 64;
        float d = q0 * kp[lane] + q1 * kp[lane + 32];
        #pragma unroll
        for (int off = 16; off > 0; off >>= 1)
            d += __shfl_xor_sync(0xffffffffu, d, off);
        float s  = d + bp[j];
        float mn = fmaxf(m, s);
        float corr = __expf(m - mn);
        float w    = __expf(s - mn);
        lsum = lsum * corr + w;
        o0 = o0 * corr + w * Vb[(size_t)j * 64 + lane];
        o1 = o1 * corr + w * Vb[(size_t)j * 64 + lane + 32];
        m = mn;
    }
    float inv = 1.f / lsum;
    float* op = g_O + ((size_t)(b * NN + i)) * 512 + h * 64;
    op[lane] = o0 * inv;
    op[lane + 32] = o1 * inv;
}

// ---------------- GLU: ag = a * silu(g) ----------------------------------
__global__ void glu_kernel() {
    int idx = blockIdx.x * blockDim.x + threadIdx.x;
    if (idx >= MM * FFD) return;
    int r = idx / FFD, c = idx % FFD;
    float a = g_Hb[(size_t)r * 2 * FFD + c];
    float g = g_Hb[(size_t)r * 2 * FFD + FFD + c];
    g_AG[idx] = a * g / (1.f + expf(-g));
}

// ---------------- copy -----------------------------------------------------
__global__ void copy_kernel(const float* __restrict__ src, float* __restrict__ dst, int n) {
    int idx = blockIdx.x * blockDim.x + threadIdx.x;
    if (idx < n) dst[idx] = src[idx];
}

// ---------------- host orchestration --------------------------------------
static inline void run_gemm(const float* A, const float* B, const float* bias,
                            float* C, int M, int N, int K, int acc) {
    dim3 grid(N / GBN, (M + GBM - 1) / GBM);
    bgemm_kernel<<<grid, 256>>>(A, B, bias, C, M, N, K, acc);
}

extern "C" void kernel_launch(void* const* d_in, const int* in_sizes, int n_in,
                              void* d_out, int out_size) {
    (void)in_sizes; (void)n_in; (void)out_size;
    const float* x            = (const float*)d_in[0];
    const float* attn_norm_g  = (const float*)d_in[1];
    const float* Wq           = (const float*)d_in[2];
    const float* Wkv          = (const float*)d_in[3];
    const float* bkv          = (const float*)d_in[4];
    const float* null_kv      = (const float*)d_in[5];
    const float* Wo           = (const float*)d_in[6];
    const float* out_norm_g   = (const float*)d_in[7];
    const float* ff_norm_g    = (const float*)d_in[8];
    const float* Wff1         = (const float*)d_in[9];
    const float* Wff2         = (const float*)d_in[10];
    const float* relpos       = (const float*)d_in[11];
    const float* final_norm_g = (const float*)d_in[12];
    const float* Wproj        = (const float*)d_in[13];
    float* out = (float*)d_out;

    float *X, *XN, *Q, *KV, *T, *O, *Hb, *AG;
    cudaGetSymbolAddress((void**)&X,  g_X);
    cudaGetSymbolAddress((void**)&XN, g_XN);
    cudaGetSymbolAddress((void**)&Q,  g_Q);
    cudaGetSymbolAddress((void**)&KV, g_KV);
    cudaGetSymbolAddress((void**)&T,  g_T);
    cudaGetSymbolAddress((void**)&O,  g_O);
    cudaGetSymbolAddress((void**)&Hb, g_Hb);
    cudaGetSymbolAddress((void**)&AG, g_AG);

    copy_kernel<<<(MM * DD + 255) / 256, 256>>>(x, X, MM * DD);
    rope_kernel<<<(NN * 16 + 255) / 256, 256>>>();
    bias_kernel<<<(NN * NKV + 255) / 256, 256>>>(relpos);

    for (int l = 0; l < LL; l++) {
        // attention block
        ln_kernel<<<MM, 256>>>(X, attn_norm_g + (size_t)l * DD, XN, 0);
        run_gemm(XN, Wq  + (size_t)l * DD * 512, nullptr,          Q,  MM, 512, DD, 0);
        run_gemm(XN, Wkv + (size_t)l * DD * 128, bkv + l * 128,    KV, MM, 128, DD, 0);
        qpost_kernel<<<(MM * HH * 32 + 255) / 256, 256>>>();
        kvpost_kernel<<<(BB * NKV * 32 + 255) / 256, 256>>>(null_kv + (size_t)l * 128);
        attn_kernel<<<(BB * HH * NN * 32 + 255) / 256, 256>>>();
        run_gemm(O, Wo + (size_t)l * 512 * DD, nullptr, T, MM, DD, 512, 0);
        ln_kernel<<<MM, 256>>>(T, out_norm_g + (size_t)l * DD, X, 1);
        // ff block
        ln_kernel<<<MM, 256>>>(X, ff_norm_g + (size_t)l * DD, XN, 0);
        run_gemm(XN, Wff1 + (size_t)l * DD * 2 * FFD, nullptr, Hb, MM, 2 * FFD, DD, 0);
        glu_kernel<<<(MM * FFD + 255) / 256, 256>>>();
        run_gemm(AG, Wff2 + (size_t)l * FFD * DD, nullptr, X, MM, DD, FFD, 1);
    }

    ln_kernel<<<MM, 256>>>(X, final_norm_g, XN, 2);
    run_gemm(XN, Wproj, nullptr, out, MM, DD, DD, 0);
}

// round 4
// speedup vs baseline: 2.3378x; 1.0024x over previous
#include <cuda_runtime.h>
#include <cuda_bf16.h>
#include <math.h>
#include <float.h>
#include <stdint.h>

// ---------------- problem constants ----------------
#define BB   8
#define NN   515
#define DD   1024
#define HH   8
#define DHE  64
#define LL   4
#define FFD  4096
#define NKV  516              // N + 1 (null kv prepended)
#define MM   (BB*NN)          // 4120 tokens
#define EPSL 1e-5f

// ---------------- scratch (static device globals; no allocs allowed) ------
__device__ float g_X  [MM*DD];
__device__ float g_XN [MM*DD];
__device__ float g_Q  [MM*512];
__device__ float g_KV [MM*128];
__device__ float g_K  [BB*NKV*DHE];
__device__ float g_V  [BB*NKV*DHE];
__device__ float g_O  [MM*512];
__device__ float g_T  [MM*DD];
__device__ float g_Hb [MM*2*FFD];
__device__ float g_AG [MM*FFD];
__device__ float g_bias[HH*NN*NKV];
__device__ float g_cos[NN*16];
__device__ float g_sin[NN*16];

// ---------------- reductions ----------------
__device__ __forceinline__ float warpReduceSum(float v) {
    #pragma unroll
    for (int o = 16; o > 0; o >>= 1) v += __shfl_xor_sync(0xffffffffu, v, o);
    return v;
}
__device__ __forceinline__ float warpReduceMax(float v) {
    #pragma unroll
    for (int o = 16; o > 0; o >>= 1) v = fmaxf(v, __shfl_xor_sync(0xffffffffu, v, o));
    return v;
}
__device__ __forceinline__ float blockReduceSum(float v) {
    __shared__ float sh[8];
    int lane = threadIdx.x & 31, w = threadIdx.x >> 5;
    v = warpReduceSum(v);
    __syncthreads();
    if (lane == 0) sh[w] = v;
    __syncthreads();
    if (w == 0) {
        float t = (lane < 8) ? sh[lane] : 0.f;
        t = warpReduceSum(t);
        if (lane == 0) sh[0] = t;
    }
    __syncthreads();
    return sh[0];
}
__device__ __forceinline__ float blockReduceMax(float v) {
    __shared__ float sh[8];
    int lane = threadIdx.x & 31, w = threadIdx.x >> 5;
    v = warpReduceMax(v);
    __syncthreads();
    if (lane == 0) sh[w] = v;
    __syncthreads();
    if (w == 0) {
        float t = (lane < 8) ? sh[lane] : -FLT_MAX;
        t = warpReduceMax(t);
        if (lane == 0) sh[0] = t;
    }
    __syncthreads();
    return sh[0];
}

// ================= split-bf16 tensor-core GEMM =============================
// C[M,N] = A[M,K] @ B[K,N] (+bias) (+=), fp32 in/out.
// Each fp32 x split as x = hi + lo (both bf16). D += Ah*Bh + Ah*Bl + Al*Bh
// with mma.sync.m16n8k16.bf16, fp32 accum. Per-product err ~1e-5.
// CTA tile 128x128, GBK=32 floats (16 k-pairs), 8 warps, warp tile 64x32.
// Register double-buffering of global loads.
#define GBM 128
#define GBN 128
#define GBK 32
#define ASTR 136
#define BSTR 136

__device__ __forceinline__ uint32_t pack_hi(float x, float y, float& rx, float& ry) {
    __nv_bfloat162 h = __floats2bfloat162_rn(x, y);
    rx = x - __bfloat162float(h.x);
    ry = y - __bfloat162float(h.y);
    return *(uint32_t*)&h;
}
__device__ __forceinline__ uint32_t pack_bf(float x, float y) {
    __nv_bfloat162 h = __floats2bfloat162_rn(x, y);
    return *(uint32_t*)&h;
}
__device__ __forceinline__ void mma_bf16(float* c, const uint32_t* a, const uint32_t* b) {
    asm volatile(
        "mma.sync.aligned.m16n8k16.row.col.f32.bf16.bf16.f32 "
        "{%0,%1,%2,%3}, {%4,%5,%6,%7}, {%8,%9}, {%0,%1,%2,%3};"
        : "+f"(c[0]), "+f"(c[1]), "+f"(c[2]), "+f"(c[3])
        : "r"(a[0]), "r"(a[1]), "r"(a[2]), "r"(a[3]), "r"(b[0]), "r"(b[1]));
}

__global__ __launch_bounds__(256)
void bgemm_kernel(const float* __restrict__ A, const float* __restrict__ B,
                  const float* __restrict__ bias, float* __restrict__ C,
                  int M, int N, int K, int accumulate)
{
    __shared__ uint32_t Ah[16][ASTR], Al[16][ASTR];
    __shared__ uint32_t Bh[16][BSTR], Bl[16][BSTR];

    const int tid  = threadIdx.x;
    const int lane = tid & 31;
    const int warp = tid >> 5;
    const int gid  = lane >> 2;
    const int tig  = lane & 3;
    const int warp_row = (warp & 1) * 64;
    const int warp_col = (warp >> 1) * 32;
    const int block_row = blockIdx.y * GBM;
    const int block_col = blockIdx.x * GBN;

    // ---- loader index precompute
    int aRow[4], aK2[4];
    #pragma unroll
    for (int i = 0; i < 4; i++) {
        int idx = tid + i * 256;        // 1024 float4 units (128 rows x 8)
        aRow[i] = idx >> 3;
        aK2[i]  = (idx & 7) * 2;        // pair index (even)
    }
    int bKp[2], bNq[2];
    #pragma unroll
    for (int p = 0; p < 2; p++) {
        int u = tid + p * 256;          // 512 units (16 kp x 32 nq)
        bKp[p] = u >> 5;
        bNq[p] = u & 31;
    }

    float4 aP[4];
    float4 bP[2][2];

    // prefetch chunk 0
    #pragma unroll
    for (int i = 0; i < 4; i++) {
        int gr = block_row + aRow[i];
        aP[i] = (gr < M) ? *(const float4*)&A[(size_t)gr * K + aK2[i] * 2]
                         : make_float4(0.f, 0.f, 0.f, 0.f);
    }
    #pragma unroll
    for (int p = 0; p < 2; p++) {
        const float* bp = &B[(size_t)(2 * bKp[p]) * N + block_col + bNq[p] * 4];
        bP[p][0] = *(const float4*)bp;
        bP[p][1] = *(const float4*)(bp + N);
    }

    float acc[4][4][4];
    #pragma unroll
    for (int a = 0; a < 4; a++)
        #pragma unroll
        for (int b = 0; b < 4; b++)
            #pragma unroll
            for (int c = 0; c < 4; c++) acc[a][b][c] = 0.f;

    for (int k0 = 0; k0 < K; k0 += GBK) {
        __syncthreads();
        // ---- convert prefetched regs -> split bf16 smem
        #pragma unroll
        for (int i = 0; i < 4; i++) {
            float rx, ry, rz, rw;
            uint32_t h0 = pack_hi(aP[i].x, aP[i].y, rx, ry);
            uint32_t h1 = pack_hi(aP[i].z, aP[i].w, rz, rw);
            Ah[aK2[i]    ][aRow[i]] = h0;
            Ah[aK2[i] + 1][aRow[i]] = h1;
            Al[aK2[i]    ][aRow[i]] = pack_bf(rx, ry);
            Al[aK2[i] + 1][aRow[i]] = pack_bf(rz, rw);
        }
        #pragma unroll
        for (int p = 0; p < 2; p++) {
            uint32_t h[4], l[4];
            const float* u = (const float*)&bP[p][0];
            const float* w = (const float*)&bP[p][1];
            #pragma unroll
            for (int j = 0; j < 4; j++) {
                float rx, ry;
                h[j] = pack_hi(u[j], w[j], rx, ry);
                l[j] = pack_bf(rx, ry);
            }
            *(uint4*)&Bh[bKp[p]][bNq[p] * 4] = make_uint4(h[0], h[1], h[2], h[3]);
            *(uint4*)&Bl[bKp[p]][bNq[p] * 4] = make_uint4(l[0], l[1], l[2], l[3]);
        }
        __syncthreads();

        // ---- prefetch next chunk
        if (k0 + GBK < K) {
            #pragma unroll
            for (int i = 0; i < 4; i++) {
                int gr = block_row + aRow[i];
                aP[i] = (gr < M) ? *(const float4*)&A[(size_t)gr * K + k0 + GBK + aK2[i] * 2]
                                 : make_float4(0.f, 0.f, 0.f, 0.f);
            }
            #pragma unroll
            for (int p = 0; p < 2; p++) {
                const float* bp = &B[(size_t)(k0 + GBK + 2 * bKp[p]) * N + block_col + bNq[p] * 4];
                bP[p][0] = *(const float4*)bp;
                bP[p][1] = *(const float4*)(bp + N);
            }
        }

        // ---- compute: two k16 steps
        #pragma unroll
        for (int kk2 = 0; kk2 < 16; kk2 += 8) {
            uint32_t ah[4][4], al[4][4], bh[4][2], bl[4][2];
            #pragma unroll
            for (int mt = 0; mt < 4; mt++) {
                int m0 = warp_row + mt * 16 + gid;
                ah[mt][0] = Ah[kk2 + tig    ][m0    ];
                ah[mt][1] = Ah[kk2 + tig    ][m0 + 8];
                ah[mt][2] = Ah[kk2 + tig + 4][m0    ];
                ah[mt][3] = Ah[kk2 + tig + 4][m0 + 8];
                al[mt][0] = Al[kk2 + tig    ][m0    ];
                al[mt][1] = Al[kk2 + tig    ][m0 + 8];
                al[mt][2] = Al[kk2 + tig + 4][m0    ];
                al[mt][3] = Al[kk2 + tig + 4][m0 + 8];
            }
            #pragma unroll
            for (int nt = 0; nt < 4; nt++) {
                int n0 = warp_col + nt * 8 + gid;
                bh[nt][0] = Bh[kk2 + tig    ][n0];
                bh[nt][1] = Bh[kk2 + tig + 4][n0];
                bl[nt][0] = Bl[kk2 + tig    ][n0];
                bl[nt][1] = Bl[kk2 + tig + 4][n0];
            }
            #pragma unroll
            for (int mt = 0; mt < 4; mt++)
                #pragma unroll
                for (int nt = 0; nt < 4; nt++) {
                    mma_bf16(acc[mt][nt], ah[mt], bh[nt]);
                    mma_bf16(acc[mt][nt], ah[mt], bl[nt]);
                    mma_bf16(acc[mt][nt], al[mt], bh[nt]);
                }
        }
    }

    // ---- epilogue
    #pragma unroll
    for (int mt = 0; mt < 4; mt++) {
        int r0 = block_row + warp_row + mt * 16 + gid;
        #pragma unroll
        for (int half = 0; half < 2; half++) {
            int r = r0 + half * 8;
            if (r >= M) continue;
            #pragma unroll
            for (int nt = 0; nt < 4; nt++) {
                int col = block_col + warp_col + nt * 8 + 2 * tig;
                float v0 = acc[mt][nt][half * 2 + 0];
                float v1 = acc[mt][nt][half * 2 + 1];
                if (bias) { v0 += bias[col]; v1 += bias[col + 1]; }
                float* cp = C + (size_t)r * N + col;
                if (accumulate) { cp[0] += v0; cp[1] += v1; }
                else            { cp[0]  = v0; cp[1]  = v1; }
            }
        }
    }
}

// ---------------- LayerNorm (mode 0: out = LN*g, 1: out += LN*g, 2: stable)
__global__ __launch_bounds__(256)
void ln_kernel(const float* __restrict__ in, const float* __restrict__ g,
               float* __restrict__ out, int mode)
{
    const int row = blockIdx.x;
    const float* xr = in + (size_t)row * DD;
    const int t = threadIdx.x;
    float v[4];
    #pragma unroll
    for (int i = 0; i < 4; i++) v[i] = xr[t + i * 256];

    if (mode == 2) {
        float lm = -FLT_MAX;
        #pragma unroll
        for (int i = 0; i < 4; i++) lm = fmaxf(lm, v[i]);
        float mx = blockReduceMax(lm);
        float inv = 1.f / mx;
        #pragma unroll
        for (int i = 0; i < 4; i++) v[i] *= inv;
    }
    float s = 0.f;
    #pragma unroll
    for (int i = 0; i < 4; i++) s += v[i];
    float mean = blockReduceSum(s) * (1.f / DD);
    float vs = 0.f;
    #pragma unroll
    for (int i = 0; i < 4; i++) { float d = v[i] - mean; vs += d * d; }
    float var  = blockReduceSum(vs) * (1.f / DD);
    float rstd = rsqrtf(var + EPSL);
    #pragma unroll
    for (int i = 0; i < 4; i++) {
        int c = t + i * 256;
        float y = (v[i] - mean) * rstd * g[c];
        if (mode == 1) out[(size_t)row * DD + c] += y;
        else           out[(size_t)row * DD + c]  = y;
    }
}

// ---------------- precompute: rotary tables + rel-pos bias ---------------
__global__ void rope_kernel() {
    int idx = blockIdx.x * blockDim.x + threadIdx.x;
    if (idx >= NN * 16) return;
    int p = idx >> 4, i = idx & 15;
    float inv = powf(10000.f, -(float)(2 * i) / 32.f);
    float fr  = (float)p * inv;
    g_cos[idx] = cosf(fr);
    g_sin[idx] = sinf(fr);
}

__global__ void bias_kernel(const float* __restrict__ emb) {
    int idx = blockIdx.x * blockDim.x + threadIdx.x;
    if (idx >= NN * NKV) return;
    int i = idx / NKV, j = idx % NKV;
    int nn = max(i - j, 0);
    int bucket;
    if (nn < 16) bucket = nn;
    else {
        float nf = (float)nn;
        int vl = 16 + (int)(logf(nf * (1.f / 16.f)) / logf(8.f) * 16.f);
        bucket = min(vl, 31);
    }
    #pragma unroll
    for (int h = 0; h < HH; h++)
        g_bias[((size_t)h * NN + i) * NKV + j] = emb[bucket * HH + h];
}

// ---------------- q post: rotary + l2norm * 4 ----------------------------
__global__ __launch_bounds__(256)
void qpost_kernel() {
    int gw   = (blockIdx.x * blockDim.x + threadIdx.x) >> 5;
    int lane = threadIdx.x & 31;
    if (gw >= MM * HH) return;
    int m = gw / HH, h = gw % HH;
    int pos = m % NN;
    float* qp = g_Q + (size_t)m * 512 + h * 64;
    float q0 = qp[lane], q1 = qp[lane + 32];
    float c = g_cos[pos * 16 + (lane >> 1)];
    float s = g_sin[pos * 16 + (lane >> 1)];
    float part = __shfl_xor_sync(0xffffffffu, q0, 1);
    q0 = (lane & 1) ? fmaf(q0, c, part * s) : fmaf(q0, c, -part * s);
    float nrm = warpReduceSum(q0 * q0 + q1 * q1);
    float inv = 4.f * rsqrtf(nrm);
    qp[lane] = q0 * inv;
    qp[lane + 32] = q1 * inv;
}

// ---------------- kv post: rotary on k, prepend null kv, l2norm(k)*4 -----
__global__ __launch_bounds__(256)
void kvpost_kernel(const float* __restrict__ nullkv) {
    int gw   = (blockIdx.x * blockDim.x + threadIdx.x) >> 5;
    int lane = threadIdx.x & 31;
    if (gw >= BB * NKV) return;
    int b = gw / NKV, j = gw % NKV;
    float k0, k1, v0, v1;
    if (j == 0) {
        k0 = nullkv[lane];      k1 = nullkv[lane + 32];
        v0 = nullkv[64 + lane]; v1 = nullkv[96 + lane];
    } else {
        int pos = j - 1;
        const float* kv = g_KV + ((size_t)(b * NN + pos)) * 128;
        k0 = kv[lane];      k1 = kv[lane + 32];
        v0 = kv[64 + lane]; v1 = kv[96 + lane];
        float c = g_cos[pos * 16 + (lane >> 1)];
        float s = g_sin[pos * 16 + (lane >> 1)];
        float part = __shfl_xor_sync(0xffffffffu, k0, 1);
        k0 = (lane & 1) ? fmaf(k0, c, part * s) : fmaf(k0, c, -part * s);
    }
    float nrm = warpReduceSum(k0 * k0 + k1 * k1);
    float inv = 4.f * rsqrtf(nrm);
    size_t o = ((size_t)(b * NKV + j)) * 64;
    g_K[o + lane] = k0 * inv;  g_K[o + lane + 32] = k1 * inv;
    g_V[o + lane] = v0;        g_V[o + lane + 32] = v1;
}

// ---------------- attention: one warp per (b,h,i), online softmax --------
__global__ __launch_bounds__(256)
void attn_kernel() {
    int gw   = (blockIdx.x * blockDim.x + threadIdx.x) >> 5;
    int lane = threadIdx.x & 31;
    if (gw >= BB * HH * NN) return;
    int i  = gw % NN;
    int bh = gw / NN;
    int h  = bh % HH, b = bh / HH;

    const float* qp = g_Q + ((size_t)(b * NN + i)) * 512 + h * 64;
    float q0 = qp[lane], q1 = qp[lane + 32];
    const float* Kb = g_K + (size_t)b * NKV * 64;
    const float* Vb = g_V + (size_t)b * NKV * 64;
    const float* bp = g_bias + ((size_t)h * NN + i) * NKV;

    float m = -1e30f, lsum = 0.f, o0 = 0.f, o1 = 0.f;
    int jmax = i + 1;
    for (int j = 0; j <= jmax; j++) {
        const float* kp = Kb + (size_t)j * 64;
        float d = q0 * kp[lane] + q1 * kp[lane + 32];
        #pragma unroll
        for (int off = 16; off > 0; off >>= 1)
            d += __shfl_xor_sync(0xffffffffu, d, off);
        float s  = d + bp[j];
        float mn = fmaxf(m, s);
        float corr = __expf(m - mn);
        float w    = __expf(s - mn);
        lsum = lsum * corr + w;
        o0 = o0 * corr + w * Vb[(size_t)j * 64 + lane];
        o1 = o1 * corr + w * Vb[(size_t)j * 64 + lane + 32];
        m = mn;
    }
    float inv = 1.f / lsum;
    float* op = g_O + ((size_t)(b * NN + i)) * 512 + h * 64;
    op[lane] = o0 * inv;
    op[lane + 32] = o1 * inv;
}

// ---------------- GLU: ag = a * silu(g) ----------------------------------
__global__ void glu_kernel() {
    int idx = blockIdx.x * blockDim.x + threadIdx.x;
    if (idx >= MM * FFD) return;
    int r = idx / FFD, c = idx % FFD;
    float a = g_Hb[(size_t)r * 2 * FFD + c];
    float g = g_Hb[(size_t)r * 2 * FFD + FFD + c];
    g_AG[idx] = a * g / (1.f + expf(-g));
}

// ---------------- copy -----------------------------------------------------
__global__ void copy_kernel(const float* __restrict__ src, float* __restrict__ dst, int n) {
    int idx = blockIdx.x * blockDim.x + threadIdx.x;
    if (idx < n) dst[idx] = src[idx];
}

// ---------------- host orchestration --------------------------------------
static inline void run_gemm(const float* A, const float* B, const float* bias,
                            float* C, int M, int N, int K, int acc) {
    dim3 grid(N / GBN, (M + GBM - 1) / GBM);
    bgemm_kernel<<<grid, 256>>>(A, B, bias, C, M, N, K, acc);
}

extern "C" void kernel_launch(void* const* d_in, const int* in_sizes, int n_in,
                              void* d_out, int out_size) {
    (void)in_sizes; (void)n_in; (void)out_size;
    const float* x            = (const float*)d_in[0];
    const float* attn_norm_g  = (const float*)d_in[1];
    const float* Wq           = (const float*)d_in[2];
    const float* Wkv          = (const float*)d_in[3];
    const float* bkv          = (const float*)d_in[4];
    const float* null_kv      = (const float*)d_in[5];
    const float* Wo           = (const float*)d_in[6];
    const float* out_norm_g   = (const float*)d_in[7];
    const float* ff_norm_g    = (const float*)d_in[8];
    const float* Wff1         = (const float*)d_in[9];
    const float* Wff2         = (const float*)d_in[10];
    const float* relpos       = (const float*)d_in[11];
    const float* final_norm_g = (const float*)d_in[12];
    const float* Wproj        = (const float*)d_in[13];
    float* out = (float*)d_out;

    float *X, *XN, *Q, *KV, *T, *O, *Hb, *AG;
    cudaGetSymbolAddress((void**)&X,  g_X);
    cudaGetSymbolAddress((void**)&XN, g_XN);
    cudaGetSymbolAddress((void**)&Q,  g_Q);
    cudaGetSymbolAddress((void**)&KV, g_KV);
    cudaGetSymbolAddress((void**)&T,  g_T);
    cudaGetSymbolAddress((void**)&O,  g_O);
    cudaGetSymbolAddress((void**)&Hb, g_Hb);
    cudaGetSymbolAddress((void**)&AG, g_AG);

    copy_kernel<<<(MM * DD + 255) / 256, 256>>>(x, X, MM * DD);
    rope_kernel<<<(NN * 16 + 255) / 256, 256>>>();
    bias_kernel<<<(NN * NKV + 255) / 256, 256>>>(relpos);

    for (int l = 0; l < LL; l++) {
        // attention block
        ln_kernel<<<MM, 256>>>(X, attn_norm_g + (size_t)l * DD, XN, 0);
        run_gemm(XN, Wq  + (size_t)l * DD * 512, nullptr,          Q,  MM, 512, DD, 0);
        run_gemm(XN, Wkv + (size_t)l * DD * 128, bkv + l * 128,    KV, MM, 128, DD, 0);
        qpost_kernel<<<(MM * HH * 32 + 255) / 256, 256>>>();
        kvpost_kernel<<<(BB * NKV * 32 + 255) / 256, 256>>>(null_kv + (size_t)l * 128);
        attn_kernel<<<(BB * HH * NN * 32 + 255) / 256, 256>>>();
        run_gemm(O, Wo + (size_t)l * 512 * DD, nullptr, T, MM, DD, 512, 0);
        ln_kernel<<<MM, 256>>>(T, out_norm_g + (size_t)l * DD, X, 1);
        // ff block
        ln_kernel<<<MM, 256>>>(X, ff_norm_g + (size_t)l * DD, XN, 0);
        run_gemm(XN, Wff1 + (size_t)l * DD * 2 * FFD, nullptr, Hb, MM, 2 * FFD, DD, 0);
        glu_kernel<<<(MM * FFD + 255) / 256, 256>>>();
        run_gemm(AG, Wff2 + (size_t)l * FFD * DD, nullptr, X, MM, DD, FFD, 1);
    }

    ln_kernel<<<MM, 256>>>(X, final_norm_g, XN, 2);
    run_gemm(XN, Wproj, nullptr, out, MM, DD, DD, 0);
}

// round 6
// speedup vs baseline: 2.5876x; 1.1069x over previous
#include <cuda_runtime.h>
#include <cuda_bf16.h>
#include <math.h>
#include <float.h>
#include <stdint.h>

#define BB   8
#define NN   515
#define DD   1024
#define HH   8
#define LL   4
#define FFD  4096
#define NKV  516
#define MM   (BB*NN)
#define EPSL 1e-5f

// ---------------- scratch ----------------
__device__ float g_X [MM*DD];
__device__ float g_Q [MM*512];
__device__ float g_KV[MM*128];
__device__ float g_K [BB*NKV*64];
__device__ float g_V [BB*NKV*64];
__device__ float g_T [MM*DD];
__device__ float g_Hb[(size_t)MM*2*FFD];
__device__ float g_bias[HH*NN*NKV];
__device__ float g_cos[NN*16];
__device__ float g_sin[NN*16];
__device__ __nv_bfloat16 g_XNh[MM*DD],  g_XNl[MM*DD];
__device__ __nv_bfloat16 g_Oh [MM*512], g_Ol [MM*512];
__device__ __nv_bfloat16 g_AGh[(size_t)MM*FFD], g_AGl[(size_t)MM*FFD];
__device__ __nv_bfloat16 g_WqTh [LL*512*DD],  g_WqTl [LL*512*DD];
__device__ __nv_bfloat16 g_WkvTh[LL*128*DD],  g_WkvTl[LL*128*DD];
__device__ __nv_bfloat16 g_WoTh [LL*DD*512],  g_WoTl [LL*DD*512];
__device__ __nv_bfloat16 g_Wff1Th[(size_t)LL*2*FFD*DD], g_Wff1Tl[(size_t)LL*2*FFD*DD];
__device__ __nv_bfloat16 g_Wff2Th[(size_t)LL*DD*FFD],   g_Wff2Tl[(size_t)LL*DD*FFD];
__device__ __nv_bfloat16 g_WprojTh[DD*DD], g_WprojTl[DD*DD];

// ---------------- small helpers ----------------
__device__ __forceinline__ uint32_t smem_u32(const void* p) {
    uint32_t a;
    asm("{ .reg .u64 t; cvta.to.shared.u64 t, %1; cvt.u32.u64 %0, t; }" : "=r"(a) : "l"(p));
    return a;
}
__device__ __forceinline__ void cp16(uint32_t dst, const void* src, bool pred) {
    int sz = pred ? 16 : 0;
    asm volatile("cp.async.cg.shared.global [%0], [%1], 16, %2;\n" :: "r"(dst), "l"(src), "r"(sz));
}
__device__ __forceinline__ void cp_commit() {
    asm volatile("cp.async.commit_group;\n" ::: "memory");
}
template<int N>
__device__ __forceinline__ void cp_wait() {
    asm volatile("cp.async.wait_group %0;\n" :: "n"(N) : "memory");
}
__device__ __forceinline__ void ldsm4(uint32_t* r, uint32_t addr) {
    asm volatile("ldmatrix.sync.aligned.m8n8.x4.shared.b16 {%0,%1,%2,%3}, [%4];"
                 : "=r"(r[0]), "=r"(r[1]), "=r"(r[2]), "=r"(r[3]) : "r"(addr));
}
__device__ __forceinline__ void mma_bf16(float* c, const uint32_t* a, const uint32_t* b) {
    asm volatile(
        "mma.sync.aligned.m16n8k16.row.col.f32.bf16.bf16.f32 "
        "{%0,%1,%2,%3}, {%4,%5,%6,%7}, {%8,%9}, {%0,%1,%2,%3};"
        : "+f"(c[0]), "+f"(c[1]), "+f"(c[2]), "+f"(c[3])
        : "r"(a[0]), "r"(a[1]), "r"(a[2]), "r"(a[3]), "r"(b[0]), "r"(b[1]));
}

// ============ mma.sync split-bf16 GEMM: C[M,N] = A[M,K] @ B[N,K]^T =========
// A,B given as bf16 hi/lo pairs (preconverted). fp32 accum, 3 terms.
// CTA 128x128, k-chunk 32, 8 warps (2x4), warp tile 64x32.
// cp.async double-buffered smem, ldmatrix fragments.
// Smem tile layout: rows (m or n) x 32 halves, row stride 40 halves (80B) --
// conflict-free for ldmatrix (8 rows -> chunks row*5 mod 32 all distinct).
#define TILE_HB   (128*40*2)            // bytes per tile (128 rows x 40 halves x 2B)
#define STAGE_B   (4*TILE_HB)           // Ah,Al,Bh,Bl
#define SMEM_TOT  (2*STAGE_B)           // 81920

__global__ __launch_bounds__(256)
void bgemm_kernel(const __nv_bfloat16* __restrict__ Ah, const __nv_bfloat16* __restrict__ Al,
                  const __nv_bfloat16* __restrict__ Bh, const __nv_bfloat16* __restrict__ Bl,
                  const float* __restrict__ bias, float* __restrict__ C,
                  int M, int N, int K, int accumulate)
{
    extern __shared__ char smem[];
    const uint32_t sbase = smem_u32(smem);

    const int tid  = threadIdx.x;
    const int lane = tid & 31;
    const int warp = tid >> 5;
    const int warp_row = (warp & 1) * 64;
    const int warp_col = (warp >> 1) * 32;
    const int block_row = blockIdx.y * 128;
    const int block_col = blockIdx.x * 128;
    const int KC = K >> 5;

    // loader mapping: 2 granules of 16B per thread per tile
    const int g0row = tid >> 2;            // granule row for p=0 (g = tid)
    const int g0c   = (tid & 3) * 8;       // halves offset within row
    const int g1row = (tid + 256) >> 2;
    const int g1c   = g0c;
    const bool a0ok = true, a1ok = true;   // row bounds checked vs M at runtime

    // fragment smem addresses (byte offsets within a stage)
    // A tiles at 0 (hi) / TILE_HB (lo); B at 2*TILE_HB (hi) / 3*TILE_HB (lo)
    const int aRow = (lane & 15);
    const int aColH = (lane >> 4) << 3;              // 0 or 8 halves
    const int bRow = ((lane >> 4) << 3) + (lane & 7);
    const int bColH = ((lane >> 3) & 1) << 3;

    float acc[4][4][4];
    #pragma unroll
    for (int a = 0; a < 4; a++)
        #pragma unroll
        for (int b = 0; b < 4; b++)
            #pragma unroll
            for (int c = 0; c < 4; c++) acc[a][b][c] = 0.f;

    // ---- async load of one chunk into stage s
    auto load_chunk = [&](int s, int k0) {
        const uint32_t st = sbase + s * STAGE_B;
        // A hi/lo
        {
            int r0 = block_row + g0row, r1 = block_row + g1row;
            bool p0 = r0 < M, p1 = r1 < M;
            const __nv_bfloat16* s00 = Ah + (size_t)r0 * K + k0 + g0c;
            const __nv_bfloat16* s01 = Ah + (size_t)r1 * K + k0 + g1c;
            const __nv_bfloat16* s10 = Al + (size_t)r0 * K + k0 + g0c;
            const __nv_bfloat16* s11 = Al + (size_t)r1 * K + k0 + g1c;
            cp16(st + (g0row * 40 + g0c) * 2, s00, p0);
            cp16(st + (g1row * 40 + g1c) * 2, s01, p1);
            cp16(st + TILE_HB + (g0row * 40 + g0c) * 2, s10, p0);
            cp16(st + TILE_HB + (g1row * 40 + g1c) * 2, s11, p1);
        }
        // B hi/lo (N is multiple of 128 -> always in range)
        {
            int r0 = block_col + g0row, r1 = block_col + g1row;
            const __nv_bfloat16* s00 = Bh + (size_t)r0 * K + k0 + g0c;
            const __nv_bfloat16* s01 = Bh + (size_t)r1 * K + k0 + g1c;
            const __nv_bfloat16* s10 = Bl + (size_t)r0 * K + k0 + g0c;
            const __nv_bfloat16* s11 = Bl + (size_t)r1 * K + k0 + g1c;
            cp16(st + 2 * TILE_HB + (g0row * 40 + g0c) * 2, s00, true);
            cp16(st + 2 * TILE_HB + (g1row * 40 + g1c) * 2, s01, true);
            cp16(st + 3 * TILE_HB + (g0row * 40 + g0c) * 2, s10, true);
            cp16(st + 3 * TILE_HB + (g1row * 40 + g1c) * 2, s11, true);
        }
        cp_commit();
    };

    load_chunk(0, 0);

    for (int c = 0; c < KC; ++c) {
        const int s = c & 1;
        if (c + 1 < KC) {
            load_chunk(s ^ 1, (c + 1) << 5);
            cp_wait<1>();
        } else {
            cp_wait<0>();
        }
        __syncthreads();

        const uint32_t st = sbase + s * STAGE_B;
        #pragma unroll
        for (int ks = 0; ks < 2; ks++) {
            const int k0s = ks << 4;
            uint32_t ah[4][4], al[4][4], bh[2][4], bl[2][4];
            #pragma unroll
            for (int mt = 0; mt < 4; mt++) {
                const uint32_t addr = st + ((warp_row + mt * 16 + aRow) * 40 + k0s + aColH) * 2;
                ldsm4(ah[mt], addr);
                ldsm4(al[mt], addr + TILE_HB);
            }
            #pragma unroll
            for (int np = 0; np < 2; np++) {
                const uint32_t addr = st + 2 * TILE_HB +
                    ((warp_col + np * 16 + bRow) * 40 + k0s + bColH) * 2;
                ldsm4(bh[np], addr);
                ldsm4(bl[np], addr + TILE_HB);
            }
            #pragma unroll
            for (int mt = 0; mt < 4; mt++)
                #pragma unroll
                for (int nt = 0; nt < 4; nt++) {
                    const uint32_t* bhp = &bh[nt >> 1][(nt & 1) * 2];
                    const uint32_t* blp = &bl[nt >> 1][(nt & 1) * 2];
                    mma_bf16(acc[mt][nt], ah[mt], bhp);
                    mma_bf16(acc[mt][nt], ah[mt], blp);
                    mma_bf16(acc[mt][nt], al[mt], bhp);
                }
        }
        __syncthreads();
    }

    // ---- epilogue (same fragment mapping as r3)
    const int gid = lane >> 2;
    const int tig = lane & 3;
    #pragma unroll
    for (int mt = 0; mt < 4; mt++) {
        int r0 = block_row + warp_row + mt * 16 + gid;
        #pragma unroll
        for (int half = 0; half < 2; half++) {
            int r = r0 + half * 8;
            if (r >= M) continue;
            #pragma unroll
            for (int nt = 0; nt < 4; nt++) {
                int col = block_col + warp_col + nt * 8 + 2 * tig;
                float v0 = acc[mt][nt][half * 2 + 0];
                float v1 = acc[mt][nt][half * 2 + 1];
                if (bias) { v0 += bias[col]; v1 += bias[col + 1]; }
                float* cp = C + (size_t)r * N + col;
                if (accumulate) { cp[0] += v0; cp[1] += v1; }
                else            { cp[0]  = v0; cp[1]  = v1; }
            }
        }
    }
}

// -------- weight transpose+split: W[K][N] -> Th/Tl[N][K] bf16 --------------
__global__ void wsplit_kernel(const float* __restrict__ W, __nv_bfloat16* __restrict__ Th,
                              __nv_bfloat16* __restrict__ Tl, int K, int N)
{
    __shared__ float t[32][33];
    const int nb = blockIdx.x * 32, kb = blockIdx.y * 32;
    const int x = threadIdx.x, y = threadIdx.y;
    #pragma unroll
    for (int j = 0; j < 32; j += 8)
        t[y + j][x] = W[(size_t)(kb + y + j) * N + nb + x];
    __syncthreads();
    #pragma unroll
    for (int j = 0; j < 32; j += 8) {
        const float v = t[x][y + j];
        const __nv_bfloat16 h = __float2bfloat16(v);
        const size_t o = (size_t)(nb + y + j) * K + kb + x;
        Th[o] = h;
        Tl[o] = __float2bfloat16(v - __bfloat162float(h));
    }
}

// ---------------- reductions ----------------
__device__ __forceinline__ float warpReduceSum(float v) {
    #pragma unroll
    for (int o = 16; o > 0; o >>= 1) v += __shfl_xor_sync(0xffffffffu, v, o);
    return v;
}
__device__ __forceinline__ float warpReduceMax(float v) {
    #pragma unroll
    for (int o = 16; o > 0; o >>= 1) v = fmaxf(v, __shfl_xor_sync(0xffffffffu, v, o));
    return v;
}
__device__ __forceinline__ float blockReduceSum(float v) {
    __shared__ float sh[8];
    int lane = threadIdx.x & 31, w = threadIdx.x >> 5;
    v = warpReduceSum(v);
    __syncthreads();
    if (lane == 0) sh[w] = v;
    __syncthreads();
    if (w == 0) {
        float t = (lane < 8) ? sh[lane] : 0.f;
        t = warpReduceSum(t);
        if (lane == 0) sh[0] = t;
    }
    __syncthreads();
    return sh[0];
}
__device__ __forceinline__ float blockReduceMax(float v) {
    __shared__ float sh[8];
    int lane = threadIdx.x & 31, w = threadIdx.x >> 5;
    v = warpReduceMax(v);
    __syncthreads();
    if (lane == 0) sh[w] = v;
    __syncthreads();
    if (w == 0) {
        float t = (lane < 8) ? sh[lane] : -FLT_MAX;
        t = warpReduceMax(t);
        if (lane == 0) sh[0] = t;
    }
    __syncthreads();
    return sh[0];
}

// -------- LayerNorm: mode 0 split(LN*g), 1 outf += LN*g, 2 stable split ----
__global__ __launch_bounds__(256)
void ln_kernel(const float* __restrict__ in, const float* __restrict__ g,
               float* __restrict__ outf, __nv_bfloat16* __restrict__ outh,
               __nv_bfloat16* __restrict__ outl, int mode)
{
    const int row = blockIdx.x;
    const float* xr = in + (size_t)row * DD;
    const int t = threadIdx.x;
    float v[4];
    #pragma unroll
    for (int i = 0; i < 4; i++) v[i] = xr[t + i * 256];
    if (mode == 2) {
        float lm = -FLT_MAX;
        #pragma unroll
        for (int i = 0; i < 4; i++) lm = fmaxf(lm, v[i]);
        float inv = 1.f / blockReduceMax(lm);
        #pragma unroll
        for (int i = 0; i < 4; i++) v[i] *= inv;
    }
    float s = 0.f;
    #pragma unroll
    for (int i = 0; i < 4; i++) s += v[i];
    float mean = blockReduceSum(s) * (1.f / DD);
    float vs = 0.f;
    #pragma unroll
    for (int i = 0; i < 4; i++) { float d = v[i] - mean; vs += d * d; }
    float rstd = rsqrtf(blockReduceSum(vs) * (1.f / DD) + EPSL);
    #pragma unroll
    for (int i = 0; i < 4; i++) {
        int c = t + i * 256;
        float y = (v[i] - mean) * rstd * g[c];
        size_t idx = (size_t)row * DD + c;
        if (mode == 1) outf[idx] += y;
        else {
            __nv_bfloat16 h = __float2bfloat16(y);
            outh[idx] = h;
            outl[idx] = __float2bfloat16(y - __bfloat162float(h));
        }
    }
}

// ---------------- precompute ----------------
__global__ void rope_kernel() {
    int idx = blockIdx.x * blockDim.x + threadIdx.x;
    if (idx >= NN * 16) return;
    int p = idx >> 4, i = idx & 15;
    float fr = (float)p * powf(10000.f, -(float)(2 * i) / 32.f);
    g_cos[idx] = cosf(fr);
    g_sin[idx] = sinf(fr);
}
__global__ void bias_kernel(const float* __restrict__ emb) {
    int idx = blockIdx.x * blockDim.x + threadIdx.x;
    if (idx >= NN * NKV) return;
    int i = idx / NKV, j = idx % NKV;
    int nn = max(i - j, 0);
    int bucket;
    if (nn < 16) bucket = nn;
    else {
        int vl = 16 + (int)(logf((float)nn * (1.f / 16.f)) / logf(8.f) * 16.f);
        bucket = min(vl, 31);
    }
    #pragma unroll
    for (int h = 0; h < HH; h++)
        g_bias[((size_t)h * NN + i) * NKV + j] = emb[bucket * HH + h];
}

// ---------------- q/kv post ----------------
__global__ __launch_bounds__(256)
void qpost_kernel() {
    int gw   = (blockIdx.x * blockDim.x + threadIdx.x) >> 5;
    int lane = threadIdx.x & 31;
    if (gw >= MM * HH) return;
    int m = gw / HH, h = gw % HH;
    int pos = m % NN;
    float* qp = g_Q + (size_t)m * 512 + h * 64;
    float q0 = qp[lane], q1 = qp[lane + 32];
    float c = g_cos[pos * 16 + (lane >> 1)];
    float s = g_sin[pos * 16 + (lane >> 1)];
    float part = __shfl_xor_sync(0xffffffffu, q0, 1);
    q0 = (lane & 1) ? fmaf(q0, c, part * s) : fmaf(q0, c, -part * s);
    float inv = 4.f * rsqrtf(warpReduceSum(q0 * q0 + q1 * q1));
    qp[lane] = q0 * inv;
    qp[lane + 32] = q1 * inv;
}
__global__ __launch_bounds__(256)
void kvpost_kernel(const float* __restrict__ nullkv) {
    int gw   = (blockIdx.x * blockDim.x + threadIdx.x) >> 5;
    int lane = threadIdx.x & 31;
    if (gw >= BB * NKV) return;
    int b = gw / NKV, j = gw % NKV;
    float k0, k1, v0, v1;
    if (j == 0) {
        k0 = nullkv[lane];      k1 = nullkv[lane + 32];
        v0 = nullkv[64 + lane]; v1 = nullkv[96 + lane];
    } else {
        int pos = j - 1;
        const float* kv = g_KV + ((size_t)(b * NN + pos)) * 128;
        k0 = kv[lane];      k1 = kv[lane + 32];
        v0 = kv[64 + lane]; v1 = kv[96 + lane];
        float c = g_cos[pos * 16 + (lane >> 1)];
        float s = g_sin[pos * 16 + (lane >> 1)];
        float part = __shfl_xor_sync(0xffffffffu, k0, 1);
        k0 = (lane & 1) ? fmaf(k0, c, part * s) : fmaf(k0, c, -part * s);
    }
    float inv = 4.f * rsqrtf(warpReduceSum(k0 * k0 + k1 * k1));
    size_t o = ((size_t)(b * NKV + j)) * 64;
    g_K[o + lane] = k0 * inv;  g_K[o + lane + 32] = k1 * inv;
    g_V[o + lane] = v0;        g_V[o + lane + 32] = v1;
}

// -------- attention: one warp per (b,h,i); split-bf16 output ---------------
__global__ __launch_bounds__(256)
void attn_kernel() {
    int gw   = (blockIdx.x * blockDim.x + threadIdx.x) >> 5;
    int lane = threadIdx.x & 31;
    if (gw >= BB * HH * NN) return;
    int i  = gw % NN;
    int bh = gw / NN;
    int h  = bh % HH, b = bh / HH;

    const float* qp = g_Q + ((size_t)(b * NN + i)) * 512 + h * 64;
    float q0 = qp[lane], q1 = qp[lane + 32];
    const float* Kb = g_K + (size_t)b * NKV * 64;
    const float* Vb = g_V + (size_t)b * NKV * 64;
    const float* bp = g_bias + ((size_t)h * NN + i) * NKV;

    float m = -1e30f, lsum = 0.f, o0 = 0.f, o1 = 0.f;
    int jmax = i + 1;
    for (int j = 0; j <= jmax; j++) {
        const float* kp = Kb + (size_t)j * 64;
        float d = q0 * kp[lane] + q1 * kp[lane + 32];
        #pragma unroll
        for (int off = 16; off > 0; off >>= 1)
            d += __shfl_xor_sync(0xffffffffu, d, off);
        float s  = d + bp[j];
        float mn = fmaxf(m, s);
        float corr = __expf(m - mn);
        float w    = __expf(s - mn);
        lsum = lsum * corr + w;
        o0 = o0 * corr + w * Vb[(size_t)j * 64 + lane];
        o1 = o1 * corr + w * Vb[(size_t)j * 64 + lane + 32];
        m = mn;
    }
    float inv = 1.f / lsum;
    o0 *= inv; o1 *= inv;
    size_t op = ((size_t)(b * NN + i)) * 512 + h * 64;
    __nv_bfloat16 h0 = __float2bfloat16(o0);
    __nv_bfloat16 h1 = __float2bfloat16(o1);
    g_Oh[op + lane] = h0;       g_Ol[op + lane]      = __float2bfloat16(o0 - __bfloat162float(h0));
    g_Oh[op + lane + 32] = h1;  g_Ol[op + lane + 32] = __float2bfloat16(o1 - __bfloat162float(h1));
}

// -------- GLU: split(a * silu(g)) ------------------------------------------
__global__ void glu_kernel() {
    size_t idx = (size_t)blockIdx.x * blockDim.x + threadIdx.x;
    if (idx >= (size_t)MM * FFD) return;
    size_t r = idx / FFD, c = idx % FFD;
    float a = g_Hb[r * 2 * FFD + c];
    float g = g_Hb[r * 2 * FFD + FFD + c];
    float v = a * g / (1.f + expf(-g));
    __nv_bfloat16 h = __float2bfloat16(v);
    g_AGh[idx] = h;
    g_AGl[idx] = __float2bfloat16(v - __bfloat162float(h));
}

__global__ void copy_kernel(const float* __restrict__ src, float* __restrict__ dst, int n) {
    int idx = blockIdx.x * blockDim.x + threadIdx.x;
    if (idx < n) dst[idx] = src[idx];
}

// ---------------- host orchestration --------------------------------------
static inline void run_gemm(const __nv_bfloat16* Ah, const __nv_bfloat16* Al,
                            const __nv_bfloat16* Bh, const __nv_bfloat16* Bl,
                            const float* bias, float* C, int M, int N, int K, int acc) {
    dim3 grid(N / 128, (M + 127) / 128);
    bgemm_kernel<<<grid, 256, SMEM_TOT>>>(Ah, Al, Bh, Bl, bias, C, M, N, K, acc);
}

extern "C" void kernel_launch(void* const* d_in, const int* in_sizes, int n_in,
                              void* d_out, int out_size) {
    (void)in_sizes; (void)n_in; (void)out_size;
    const float* x            = (const float*)d_in[0];
    const float* attn_norm_g  = (const float*)d_in[1];
    const float* Wq           = (const float*)d_in[2];
    const float* Wkv          = (const float*)d_in[3];
    const float* bkv          = (const float*)d_in[4];
    const float* null_kv      = (const float*)d_in[5];
    const float* Wo           = (const float*)d_in[6];
    const float* out_norm_g   = (const float*)d_in[7];
    const float* ff_norm_g    = (const float*)d_in[8];
    const float* Wff1         = (const float*)d_in[9];
    const float* Wff2         = (const float*)d_in[10];
    const float* relpos       = (const float*)d_in[11];
    const float* final_norm_g = (const float*)d_in[12];
    const float* Wproj        = (const float*)d_in[13];
    float* out = (float*)d_out;

    cudaFuncSetAttribute(bgemm_kernel, cudaFuncAttributeMaxDynamicSharedMemorySize, SMEM_TOT);

    float *X, *Q, *KV, *T, *Hb;
    __nv_bfloat16 *XNh, *XNl, *Oh, *Ol, *AGh, *AGl;
    __nv_bfloat16 *WqTh, *WqTl, *WkvTh, *WkvTl, *WoTh, *WoTl;
    __nv_bfloat16 *W1Th, *W1Tl, *W2Th, *W2Tl, *WpTh, *WpTl;
    cudaGetSymbolAddress((void**)&X,  g_X);
    cudaGetSymbolAddress((void**)&Q,  g_Q);
    cudaGetSymbolAddress((void**)&KV, g_KV);
    cudaGetSymbolAddress((void**)&T,  g_T);
    cudaGetSymbolAddress((void**)&Hb, g_Hb);
    cudaGetSymbolAddress((void**)&XNh, g_XNh); cudaGetSymbolAddress((void**)&XNl, g_XNl);
    cudaGetSymbolAddress((void**)&Oh,  g_Oh);  cudaGetSymbolAddress((void**)&Ol,  g_Ol);
    cudaGetSymbolAddress((void**)&AGh, g_AGh); cudaGetSymbolAddress((void**)&AGl, g_AGl);
    cudaGetSymbolAddress((void**)&WqTh, g_WqTh);   cudaGetSymbolAddress((void**)&WqTl, g_WqTl);
    cudaGetSymbolAddress((void**)&WkvTh, g_WkvTh); cudaGetSymbolAddress((void**)&WkvTl, g_WkvTl);
    cudaGetSymbolAddress((void**)&WoTh, g_WoTh);   cudaGetSymbolAddress((void**)&WoTl, g_WoTl);
    cudaGetSymbolAddress((void**)&W1Th, g_Wff1Th); cudaGetSymbolAddress((void**)&W1Tl, g_Wff1Tl);
    cudaGetSymbolAddress((void**)&W2Th, g_Wff2Th); cudaGetSymbolAddress((void**)&W2Tl, g_Wff2Tl);
    cudaGetSymbolAddress((void**)&WpTh, g_WprojTh); cudaGetSymbolAddress((void**)&WpTl, g_WprojTl);

    copy_kernel<<<(MM * DD + 255) / 256, 256>>>(x, X, MM * DD);
    rope_kernel<<<(NN * 16 + 255) / 256, 256>>>();
    bias_kernel<<<(NN * NKV + 255) / 256, 256>>>(relpos);

    dim3 tb(32, 8);
    for (int l = 0; l < LL; l++) {
        wsplit_kernel<<<dim3(512 / 32, DD / 32), tb>>>(Wq + (size_t)l * DD * 512,
            WqTh + (size_t)l * 512 * DD, WqTl + (size_t)l * 512 * DD, DD, 512);
        wsplit_kernel<<<dim3(128 / 32, DD / 32), tb>>>(Wkv + (size_t)l * DD * 128,
            WkvTh + (size_t)l * 128 * DD, WkvTl + (size_t)l * 128 * DD, DD, 128);
        wsplit_kernel<<<dim3(DD / 32, 512 / 32), tb>>>(Wo + (size_t)l * 512 * DD,
            WoTh + (size_t)l * DD * 512, WoTl + (size_t)l * DD * 512, 512, DD);
        wsplit_kernel<<<dim3(2 * FFD / 32, DD / 32), tb>>>(Wff1 + (size_t)l * DD * 2 * FFD,
            W1Th + (size_t)l * 2 * FFD * DD, W1Tl + (size_t)l * 2 * FFD * DD, DD, 2 * FFD);
        wsplit_kernel<<<dim3(DD / 32, FFD / 32), tb>>>(Wff2 + (size_t)l * FFD * DD,
            W2Th + (size_t)l * DD * FFD, W2Tl + (size_t)l * DD * FFD, FFD, DD);
    }
    wsplit_kernel<<<dim3(DD / 32, DD / 32), tb>>>(Wproj, WpTh, WpTl, DD, DD);

    for (int l = 0; l < LL; l++) {
        ln_kernel<<<MM, 256>>>(X, attn_norm_g + (size_t)l * DD, nullptr, XNh, XNl, 0);
        run_gemm(XNh, XNl, WqTh + (size_t)l * 512 * DD, WqTl + (size_t)l * 512 * DD,
                 nullptr, Q, MM, 512, DD, 0);
        run_gemm(XNh, XNl, WkvTh + (size_t)l * 128 * DD, WkvTl + (size_t)l * 128 * DD,
                 bkv + l * 128, KV, MM, 128, DD, 0);
        qpost_kernel<<<(MM * HH * 32 + 255) / 256, 256>>>();
        kvpost_kernel<<<(BB * NKV * 32 + 255) / 256, 256>>>(null_kv + (size_t)l * 128);
        attn_kernel<<<(BB * HH * NN * 32 + 255) / 256, 256>>>();
        run_gemm(Oh, Ol, WoTh + (size_t)l * DD * 512, WoTl + (size_t)l * DD * 512,
                 nullptr, T, MM, DD, 512, 0);
        ln_kernel<<<MM, 256>>>(T, out_norm_g + (size_t)l * DD, X, nullptr, nullptr, 1);
        ln_kernel<<<MM, 256>>>(X, ff_norm_g + (size_t)l * DD, nullptr, XNh, XNl, 0);
        run_gemm(XNh, XNl, W1Th + (size_t)l * 2 * FFD * DD, W1Tl + (size_t)l * 2 * FFD * DD,
                 nullptr, Hb, MM, 2 * FFD, DD, 0);
        glu_kernel<<<(int)(((size_t)MM * FFD + 255) / 256), 256>>>();
        run_gemm(AGh, AGl, W2Th + (size_t)l * DD * FFD, W2Tl + (size_t)l * DD * FFD,
                 nullptr, X, MM, DD, FFD, 1);
    }

    ln_kernel<<<MM, 256>>>(X, final_norm_g, nullptr, XNh, XNl, 2);
    run_gemm(XNh, XNl, WpTh, WpTl, nullptr, out, MM, DD, DD, 0);
}

// round 7
// speedup vs baseline: 2.6750x; 1.0338x over previous
#include <cuda_runtime.h>
#include <cuda_bf16.h>
#include <math.h>
#include <float.h>
#include <stdint.h>

#define BB   8
#define NN   515
#define DD   1024
#define HH   8
#define LL   4
#define FFD  4096
#define NKV  516
#define MM   (BB*NN)
#define EPSL 1e-5f

// ---------------- scratch ----------------
__device__ float g_X [MM*DD];
__device__ float g_Q [MM*512];
__device__ float g_KV[MM*128];
__device__ float g_K [BB*NKV*64];
__device__ float g_V [BB*NKV*64];
__device__ float g_T [MM*DD];
__device__ float g_bias[HH*NN*NKV];
__device__ float g_cos[NN*16];
__device__ float g_sin[NN*16];
__device__ __nv_bfloat16 g_XNh[MM*DD],  g_XNl[MM*DD];
__device__ __nv_bfloat16 g_Oh [MM*512], g_Ol [MM*512];
__device__ __nv_bfloat16 g_AGh[(size_t)MM*FFD], g_AGl[(size_t)MM*FFD];
__device__ __nv_bfloat16 g_WqTh [LL*512*DD],  g_WqTl [LL*512*DD];
__device__ __nv_bfloat16 g_WkvTh[LL*128*DD],  g_WkvTl[LL*128*DD];
__device__ __nv_bfloat16 g_WoTh [LL*DD*512],  g_WoTl [LL*DD*512];
__device__ __nv_bfloat16 g_Wff1Th[(size_t)LL*2*FFD*DD], g_Wff1Tl[(size_t)LL*2*FFD*DD];
__device__ __nv_bfloat16 g_Wff2Th[(size_t)LL*DD*FFD],   g_Wff2Tl[(size_t)LL*DD*FFD];
__device__ __nv_bfloat16 g_WprojTh[DD*DD], g_WprojTl[DD*DD];

// ---------------- small helpers ----------------
__device__ __forceinline__ uint32_t smem_u32(const void* p) {
    uint32_t a;
    asm("{ .reg .u64 t; cvta.to.shared.u64 t, %1; cvt.u32.u64 %0, t; }" : "=r"(a) : "l"(p));
    return a;
}
__device__ __forceinline__ void cp16(uint32_t dst, const void* src, bool pred) {
    int sz = pred ? 16 : 0;
    asm volatile("cp.async.cg.shared.global [%0], [%1], 16, %2;\n" :: "r"(dst), "l"(src), "r"(sz));
}
__device__ __forceinline__ void cp_commit() {
    asm volatile("cp.async.commit_group;\n" ::: "memory");
}
template<int N>
__device__ __forceinline__ void cp_wait() {
    asm volatile("cp.async.wait_group %0;\n" :: "n"(N) : "memory");
}
__device__ __forceinline__ void ldsm4(uint32_t* r, uint32_t addr) {
    asm volatile("ldmatrix.sync.aligned.m8n8.x4.shared.b16 {%0,%1,%2,%3}, [%4];"
                 : "=r"(r[0]), "=r"(r[1]), "=r"(r[2]), "=r"(r[3]) : "r"(addr));
}
__device__ __forceinline__ void mma_bf16(float* c, const uint32_t* a, const uint32_t* b) {
    asm volatile(
        "mma.sync.aligned.m16n8k16.row.col.f32.bf16.bf16.f32 "
        "{%0,%1,%2,%3}, {%4,%5,%6,%7}, {%8,%9}, {%0,%1,%2,%3};"
        : "+f"(c[0]), "+f"(c[1]), "+f"(c[2]), "+f"(c[3])
        : "r"(a[0]), "r"(a[1]), "r"(a[2]), "r"(a[3]), "r"(b[0]), "r"(b[1]));
}

// ============ mma.sync split-bf16 GEMM: C[M,N] = A[M,K] @ B[N,K]^T =========
// mode 0: C = result (+bias) ; mode 1: C += result ; mode 2: GLU epilogue
//   (N cols hold interleaved a/g pairs; out = a*silu(g) split to outh/outl,
//    output width N/2)
#define TILE_HB   (128*40*2)
#define STAGE_B   (4*TILE_HB)
#define SMEM_TOT  (2*STAGE_B)

__global__ __launch_bounds__(256, 2)
void bgemm_kernel(const __nv_bfloat16* __restrict__ Ah, const __nv_bfloat16* __restrict__ Al,
                  const __nv_bfloat16* __restrict__ Bh, const __nv_bfloat16* __restrict__ Bl,
                  const float* __restrict__ bias, float* __restrict__ C,
                  __nv_bfloat16* __restrict__ outh, __nv_bfloat16* __restrict__ outl,
                  int M, int N, int K, int mode)
{
    extern __shared__ char smem[];
    const uint32_t sbase = smem_u32(smem);

    const int tid  = threadIdx.x;
    const int lane = tid & 31;
    const int warp = tid >> 5;
    const int warp_row = (warp & 1) * 64;
    const int warp_col = (warp >> 1) * 32;
    const int block_row = blockIdx.y * 128;
    const int block_col = blockIdx.x * 128;
    const int KC = K >> 5;

    const int g0row = tid >> 2;
    const int g0c   = (tid & 3) * 8;
    const int g1row = (tid + 256) >> 2;
    const int g1c   = g0c;

    const int aRow  = (lane & 15);
    const int aColH = (lane >> 4) << 3;
    const int bRow  = ((lane >> 4) << 3) + (lane & 7);
    const int bColH = ((lane >> 3) & 1) << 3;

    float acc[4][4][4];
    #pragma unroll
    for (int a = 0; a < 4; a++)
        #pragma unroll
        for (int b = 0; b < 4; b++)
            #pragma unroll
            for (int c = 0; c < 4; c++) acc[a][b][c] = 0.f;

    auto load_chunk = [&](int s, int k0) {
        const uint32_t st = sbase + s * STAGE_B;
        {
            int r0 = block_row + g0row, r1 = block_row + g1row;
            bool p0 = r0 < M, p1 = r1 < M;
            cp16(st + (g0row * 40 + g0c) * 2, Ah + (size_t)r0 * K + k0 + g0c, p0);
            cp16(st + (g1row * 40 + g1c) * 2, Ah + (size_t)r1 * K + k0 + g1c, p1);
            cp16(st + TILE_HB + (g0row * 40 + g0c) * 2, Al + (size_t)r0 * K + k0 + g0c, p0);
            cp16(st + TILE_HB + (g1row * 40 + g1c) * 2, Al + (size_t)r1 * K + k0 + g1c, p1);
        }
        {
            int r0 = block_col + g0row, r1 = block_col + g1row;
            cp16(st + 2 * TILE_HB + (g0row * 40 + g0c) * 2, Bh + (size_t)r0 * K + k0 + g0c, true);
            cp16(st + 2 * TILE_HB + (g1row * 40 + g1c) * 2, Bh + (size_t)r1 * K + k0 + g1c, true);
            cp16(st + 3 * TILE_HB + (g0row * 40 + g0c) * 2, Bl + (size_t)r0 * K + k0 + g0c, true);
            cp16(st + 3 * TILE_HB + (g1row * 40 + g1c) * 2, Bl + (size_t)r1 * K + k0 + g1c, true);
        }
        cp_commit();
    };

    load_chunk(0, 0);

    for (int c = 0; c < KC; ++c) {
        const int s = c & 1;
        if (c + 1 < KC) {
            load_chunk(s ^ 1, (c + 1) << 5);
            cp_wait<1>();
        } else {
            cp_wait<0>();
        }
        __syncthreads();

        const uint32_t st = sbase + s * STAGE_B;
        #pragma unroll
        for (int ks = 0; ks < 2; ks++) {
            const int k0s = ks << 4;
            uint32_t ah[4][4], al[4][4], bh[2][4], bl[2][4];
            #pragma unroll
            for (int mt = 0; mt < 4; mt++) {
                const uint32_t addr = st + ((warp_row + mt * 16 + aRow) * 40 + k0s + aColH) * 2;
                ldsm4(ah[mt], addr);
                ldsm4(al[mt], addr + TILE_HB);
            }
            #pragma unroll
            for (int np = 0; np < 2; np++) {
                const uint32_t addr = st + 2 * TILE_HB +
                    ((warp_col + np * 16 + bRow) * 40 + k0s + bColH) * 2;
                ldsm4(bh[np], addr);
                ldsm4(bl[np], addr + TILE_HB);
            }
            // term-major order: same-acc reuse distance = 16 MMAs (RAW hidden)
            #pragma unroll
            for (int term = 0; term < 3; term++) {
                #pragma unroll
                for (int mt = 0; mt < 4; mt++)
                    #pragma unroll
                    for (int nt = 0; nt < 4; nt++) {
                        const uint32_t* ap = (term == 2) ? al[mt] : ah[mt];
                        const uint32_t* bp = (term == 1) ? &bl[nt >> 1][(nt & 1) * 2]
                                                         : &bh[nt >> 1][(nt & 1) * 2];
                        mma_bf16(acc[mt][nt], ap, bp);
                    }
            }
        }
        __syncthreads();
    }

    // ---- epilogue
    const int gid = lane >> 2;
    const int tig = lane & 3;
    #pragma unroll
    for (int mt = 0; mt < 4; mt++) {
        int r0 = block_row + warp_row + mt * 16 + gid;
        #pragma unroll
        for (int half = 0; half < 2; half++) {
            int r = r0 + half * 8;
            if (r >= M) continue;
            #pragma unroll
            for (int nt = 0; nt < 4; nt++) {
                int col = block_col + warp_col + nt * 8 + 2 * tig;
                float v0 = acc[mt][nt][half * 2 + 0];
                float v1 = acc[mt][nt][half * 2 + 1];
                if (mode == 2) {
                    // v0 = a, v1 = g (permuted Wff1 interleaves a/g columns)
                    float v = v0 * v1 / (1.f + __expf(-v1));
                    __nv_bfloat16 h = __float2bfloat16(v);
                    size_t o = (size_t)r * (N >> 1) + (col >> 1);
                    outh[o] = h;
                    outl[o] = __float2bfloat16(v - __bfloat162float(h));
                } else {
                    if (bias) { v0 += bias[col]; v1 += bias[col + 1]; }
                    float* cp = C + (size_t)r * N + col;
                    if (mode == 1) { cp[0] += v0; cp[1] += v1; }
                    else           { cp[0]  = v0; cp[1]  = v1; }
                }
            }
        }
    }
}

// -------- fused weight transpose+split (all weights, one launch) -----------
// W[K][N] -> Th/Tl[N][K] bf16. glu flag permutes source columns so that
// dst row 2p = a-column p, dst row 2p+1 = g-column p (FF1 interleave).
struct WDesc { const float* W; __nv_bfloat16* Th; __nv_bfloat16* Tl; int K; int N; int glu; };
struct WTable { WDesc d[21]; };

__global__ void wsplit_all_kernel(WTable tab) {
    const WDesc w = tab.d[blockIdx.y];
    const int tilesN = w.N >> 5;
    const int tilesK = w.K >> 5;
    if ((int)blockIdx.x >= tilesN * tilesK) return;
    const int nb = (blockIdx.x % tilesN) * 32;
    const int kb = (blockIdx.x / tilesN) * 32;
    __shared__ float t[32][33];
    const int x = threadIdx.x, y = threadIdx.y;
    const int n0 = nb + x;
    const int sc = w.glu ? ((n0 & 1) * FFD + (n0 >> 1)) : n0;
    #pragma unroll
    for (int j = 0; j < 32; j += 8)
        t[y + j][x] = w.W[(size_t)(kb + y + j) * w.N + sc];
    __syncthreads();
    #pragma unroll
    for (int j = 0; j < 32; j += 8) {
        const float v = t[x][y + j];
        const __nv_bfloat16 h = __float2bfloat16(v);
        const size_t o = (size_t)(nb + y + j) * w.K + kb + x;
        w.Th[o] = h;
        w.Tl[o] = __float2bfloat16(v - __bfloat162float(h));
    }
}

// ---------------- reductions ----------------
__device__ __forceinline__ float warpReduceSum(float v) {
    #pragma unroll
    for (int o = 16; o > 0; o >>= 1) v += __shfl_xor_sync(0xffffffffu, v, o);
    return v;
}
__device__ __forceinline__ float warpReduceMax(float v) {
    #pragma unroll
    for (int o = 16; o > 0; o >>= 1) v = fmaxf(v, __shfl_xor_sync(0xffffffffu, v, o));
    return v;
}
__device__ __forceinline__ float blockReduceSum(float v) {
    __shared__ float sh[8];
    int lane = threadIdx.x & 31, w = threadIdx.x >> 5;
    v = warpReduceSum(v);
    __syncthreads();
    if (lane == 0) sh[w] = v;
    __syncthreads();
    if (w == 0) {
        float t = (lane < 8) ? sh[lane] : 0.f;
        t = warpReduceSum(t);
        if (lane == 0) sh[0] = t;
    }
    __syncthreads();
    return sh[0];
}
__device__ __forceinline__ float blockReduceMax(float v) {
    __shared__ float sh[8];
    int lane = threadIdx.x & 31, w = threadIdx.x >> 5;
    v = warpReduceMax(v);
    __syncthreads();
    if (lane == 0) sh[w] = v;
    __syncthreads();
    if (w == 0) {
        float t = (lane < 8) ? sh[lane] : -FLT_MAX;
        t = warpReduceMax(t);
        if (lane == 0) sh[0] = t;
    }
    __syncthreads();
    return sh[0];
}

// -------- LayerNorm: mode 0 split(LN*g), 1 outf += LN*g, 2 stable split ----
__global__ __launch_bounds__(256)
void ln_kernel(const float* __restrict__ in, const float* __restrict__ g,
               float* __restrict__ outf, __nv_bfloat16* __restrict__ outh,
               __nv_bfloat16* __restrict__ outl, int mode)
{
    const int row = blockIdx.x;
    const float* xr = in + (size_t)row * DD;
    const int t = threadIdx.x;
    float v[4];
    #pragma unroll
    for (int i = 0; i < 4; i++) v[i] = xr[t + i * 256];
    if (mode == 2) {
        float lm = -FLT_MAX;
        #pragma unroll
        for (int i = 0; i < 4; i++) lm = fmaxf(lm, v[i]);
        float inv = 1.f / blockReduceMax(lm);
        #pragma unroll
        for (int i = 0; i < 4; i++) v[i] *= inv;
    }
    float s = 0.f;
    #pragma unroll
    for (int i = 0; i < 4; i++) s += v[i];
    float mean = blockReduceSum(s) * (1.f / DD);
    float vs = 0.f;
    #pragma unroll
    for (int i = 0; i < 4; i++) { float d = v[i] - mean; vs += d * d; }
    float rstd = rsqrtf(blockReduceSum(vs) * (1.f / DD) + EPSL);
    #pragma unroll
    for (int i = 0; i < 4; i++) {
        int c = t + i * 256;
        float y = (v[i] - mean) * rstd * g[c];
        size_t idx = (size_t)row * DD + c;
        if (mode == 1) outf[idx] += y;
        else {
            __nv_bfloat16 h = __float2bfloat16(y);
            outh[idx] = h;
            outl[idx] = __float2bfloat16(y - __bfloat162float(h));
        }
    }
}

// ---------------- precompute ----------------
__global__ void rope_kernel() {
    int idx = blockIdx.x * blockDim.x + threadIdx.x;
    if (idx >= NN * 16) return;
    int p = idx >> 4, i = idx & 15;
    float fr = (float)p * powf(10000.f, -(float)(2 * i) / 32.f);
    g_cos[idx] = cosf(fr);
    g_sin[idx] = sinf(fr);
}
__global__ void bias_kernel(const float* __restrict__ emb) {
    int idx = blockIdx.x * blockDim.x + threadIdx.x;
    if (idx >= NN * NKV) return;
    int i = idx / NKV, j = idx % NKV;
    int nn = max(i - j, 0);
    int bucket;
    if (nn < 16) bucket = nn;
    else {
        int vl = 16 + (int)(logf((float)nn * (1.f / 16.f)) / logf(8.f) * 16.f);
        bucket = min(vl, 31);
    }
    #pragma unroll
    for (int h = 0; h < HH; h++)
        g_bias[((size_t)h * NN + i) * NKV + j] = emb[bucket * HH + h];
}

// ---------------- q/kv post ----------------
__global__ __launch_bounds__(256)
void qpost_kernel() {
    int gw   = (blockIdx.x * blockDim.x + threadIdx.x) >> 5;
    int lane = threadIdx.x & 31;
    if (gw >= MM * HH) return;
    int m = gw / HH, h = gw % HH;
    int pos = m % NN;
    float* qp = g_Q + (size_t)m * 512 + h * 64;
    float q0 = qp[lane], q1 = qp[lane + 32];
    float c = g_cos[pos * 16 + (lane >> 1)];
    float s = g_sin[pos * 16 + (lane >> 1)];
    float part = __shfl_xor_sync(0xffffffffu, q0, 1);
    q0 = (lane & 1) ? fmaf(q0, c, part * s) : fmaf(q0, c, -part * s);
    float inv = 4.f * rsqrtf(warpReduceSum(q0 * q0 + q1 * q1));
    qp[lane] = q0 * inv;
    qp[lane + 32] = q1 * inv;
}
__global__ __launch_bounds__(256)
void kvpost_kernel(const float* __restrict__ nullkv) {
    int gw   = (blockIdx.x * blockDim.x + threadIdx.x) >> 5;
    int lane = threadIdx.x & 31;
    if (gw >= BB * NKV) return;
    int b = gw / NKV, j = gw % NKV;
    float k0, k1, v0, v1;
    if (j == 0) {
        k0 = nullkv[lane];      k1 = nullkv[lane + 32];
        v0 = nullkv[64 + lane]; v1 = nullkv[96 + lane];
    } else {
        int pos = j - 1;
        const float* kv = g_KV + ((size_t)(b * NN + pos)) * 128;
        k0 = kv[lane];      k1 = kv[lane + 32];
        v0 = kv[64 + lane]; v1 = kv[96 + lane];
        float c = g_cos[pos * 16 + (lane >> 1)];
        float s = g_sin[pos * 16 + (lane >> 1)];
        float part = __shfl_xor_sync(0xffffffffu, k0, 1);
        k0 = (lane & 1) ? fmaf(k0, c, part * s) : fmaf(k0, c, -part * s);
    }
    float inv = 4.f * rsqrtf(warpReduceSum(k0 * k0 + k1 * k1));
    size_t o = ((size_t)(b * NKV + j)) * 64;
    g_K[o + lane] = k0 * inv;  g_K[o + lane + 32] = k1 * inv;
    g_V[o + lane] = v0;        g_V[o + lane + 32] = v1;
}

// -------- attention: one warp per (b,h,i); split-bf16 output ---------------
__global__ __launch_bounds__(256)
void attn_kernel() {
    int gw   = (blockIdx.x * blockDim.x + threadIdx.x) >> 5;
    int lane = threadIdx.x & 31;
    if (gw >= BB * HH * NN) return;
    int i  = gw % NN;
    int bh = gw / NN;
    int h  = bh % HH, b = bh / HH;

    const float* qp = g_Q + ((size_t)(b * NN + i)) * 512 + h * 64;
    float q0 = qp[lane], q1 = qp[lane + 32];
    const float* Kb = g_K + (size_t)b * NKV * 64;
    const float* Vb = g_V + (size_t)b * NKV * 64;
    const float* bp = g_bias + ((size_t)h * NN + i) * NKV;

    float m = -1e30f, lsum = 0.f, o0 = 0.f, o1 = 0.f;
    int jmax = i + 1;
    for (int j = 0; j <= jmax; j++) {
        const float* kp = Kb + (size_t)j * 64;
        float d = q0 * kp[lane] + q1 * kp[lane + 32];
        #pragma unroll
        for (int off = 16; off > 0; off >>= 1)
            d += __shfl_xor_sync(0xffffffffu, d, off);
        float s  = d + bp[j];
        float mn = fmaxf(m, s);
        float corr = __expf(m - mn);
        float w    = __expf(s - mn);
        lsum = lsum * corr + w;
        o0 = o0 * corr + w * Vb[(size_t)j * 64 + lane];
        o1 = o1 * corr + w * Vb[(size_t)j * 64 + lane + 32];
        m = mn;
    }
    float inv = 1.f / lsum;
    o0 *= inv; o1 *= inv;
    size_t op = ((size_t)(b * NN + i)) * 512 + h * 64;
    __nv_bfloat16 h0 = __float2bfloat16(o0);
    __nv_bfloat16 h1 = __float2bfloat16(o1);
    g_Oh[op + lane] = h0;       g_Ol[op + lane]      = __float2bfloat16(o0 - __bfloat162float(h0));
    g_Oh[op + lane + 32] = h1;  g_Ol[op + lane + 32] = __float2bfloat16(o1 - __bfloat162float(h1));
}

__global__ void copy_kernel(const float* __restrict__ src, float* __restrict__ dst, int n) {
    int idx = blockIdx.x * blockDim.x + threadIdx.x;
    if (idx < n) dst[idx] = src[idx];
}

// ---------------- host orchestration --------------------------------------
static inline void run_gemm(const __nv_bfloat16* Ah, const __nv_bfloat16* Al,
                            const __nv_bfloat16* Bh, const __nv_bfloat16* Bl,
                            const float* bias, float* C,
                            __nv_bfloat16* outh, __nv_bfloat16* outl,
                            int M, int N, int K, int mode) {
    dim3 grid(N / 128, (M + 127) / 128);
    bgemm_kernel<<<grid, 256, SMEM_TOT>>>(Ah, Al, Bh, Bl, bias, C, outh, outl, M, N, K, mode);
}

extern "C" void kernel_launch(void* const* d_in, const int* in_sizes, int n_in,
                              void* d_out, int out_size) {
    (void)in_sizes; (void)n_in; (void)out_size;
    const float* x            = (const float*)d_in[0];
    const float* attn_norm_g  = (const float*)d_in[1];
    const float* Wq           = (const float*)d_in[2];
    const float* Wkv          = (const float*)d_in[3];
    const float* bkv          = (const float*)d_in[4];
    const float* null_kv      = (const float*)d_in[5];
    const float* Wo           = (const float*)d_in[6];
    const float* out_norm_g   = (const float*)d_in[7];
    const float* ff_norm_g    = (const float*)d_in[8];
    const float* Wff1         = (const float*)d_in[9];
    const float* Wff2         = (const float*)d_in[10];
    const float* relpos       = (const float*)d_in[11];
    const float* final_norm_g = (const float*)d_in[12];
    const float* Wproj        = (const float*)d_in[13];
    float* out = (float*)d_out;

    cudaFuncSetAttribute(bgemm_kernel, cudaFuncAttributeMaxDynamicSharedMemorySize, SMEM_TOT);

    float *X, *Q, *KV, *T;
    __nv_bfloat16 *XNh, *XNl, *Oh, *Ol, *AGh, *AGl;
    __nv_bfloat16 *WqTh, *WqTl, *WkvTh, *WkvTl, *WoTh, *WoTl;
    __nv_bfloat16 *W1Th, *W1Tl, *W2Th, *W2Tl, *WpTh, *WpTl;
    cudaGetSymbolAddress((void**)&X,  g_X);
    cudaGetSymbolAddress((void**)&Q,  g_Q);
    cudaGetSymbolAddress((void**)&KV, g_KV);
    cudaGetSymbolAddress((void**)&T,  g_T);
    cudaGetSymbolAddress((void**)&XNh, g_XNh); cudaGetSymbolAddress((void**)&XNl, g_XNl);
    cudaGetSymbolAddress((void**)&Oh,  g_Oh);  cudaGetSymbolAddress((void**)&Ol,  g_Ol);
    cudaGetSymbolAddress((void**)&AGh, g_AGh); cudaGetSymbolAddress((void**)&AGl, g_AGl);
    cudaGetSymbolAddress((void**)&WqTh, g_WqTh);   cudaGetSymbolAddress((void**)&WqTl, g_WqTl);
    cudaGetSymbolAddress((void**)&WkvTh, g_WkvTh); cudaGetSymbolAddress((void**)&WkvTl, g_WkvTl);
    cudaGetSymbolAddress((void**)&WoTh, g_WoTh);   cudaGetSymbolAddress((void**)&WoTl, g_WoTl);
    cudaGetSymbolAddress((void**)&W1Th, g_Wff1Th); cudaGetSymbolAddress((void**)&W1Tl, g_Wff1Tl);
    cudaGetSymbolAddress((void**)&W2Th, g_Wff2Th); cudaGetSymbolAddress((void**)&W2Tl, g_Wff2Tl);
    cudaGetSymbolAddress((void**)&WpTh, g_WprojTh); cudaGetSymbolAddress((void**)&WpTl, g_WprojTl);

    copy_kernel<<<(MM * DD + 255) / 256, 256>>>(x, X, MM * DD);        // launch 1
    rope_kernel<<<(NN * 16 + 255) / 256, 256>>>();                     // launch 2
    bias_kernel<<<(NN * NKV + 255) / 256, 256>>>(relpos);              // launch 3

    // single fused wsplit (launch 4)
    WTable tab;
    int maxTiles = 0, di = 0;
    for (int l = 0; l < LL; l++) {
        tab.d[di++] = { Wq   + (size_t)l * DD * 512,     WqTh + (size_t)l * 512 * DD,      WqTl + (size_t)l * 512 * DD,      DD,  512,     0 };
        tab.d[di++] = { Wkv  + (size_t)l * DD * 128,     WkvTh + (size_t)l * 128 * DD,     WkvTl + (size_t)l * 128 * DD,     DD,  128,     0 };
        tab.d[di++] = { Wo   + (size_t)l * 512 * DD,     WoTh + (size_t)l * DD * 512,      WoTl + (size_t)l * DD * 512,      512, DD,      0 };
        tab.d[di++] = { Wff1 + (size_t)l * DD * 2 * FFD, W1Th + (size_t)l * 2 * FFD * DD,  W1Tl + (size_t)l * 2 * FFD * DD,  DD,  2 * FFD, 1 };
        tab.d[di++] = { Wff2 + (size_t)l * FFD * DD,     W2Th + (size_t)l * DD * FFD,      W2Tl + (size_t)l * DD * FFD,      FFD, DD,      0 };
    }
    tab.d[di++] = { Wproj, WpTh, WpTl, DD, DD, 0 };
    for (int i = 0; i < 21; i++) {
        int t = (tab.d[i].N >> 5) * (tab.d[i].K >> 5);
        if (t > maxTiles) maxTiles = t;
    }
    wsplit_all_kernel<<<dim3(maxTiles, 21), dim3(32, 8)>>>(tab);

    for (int l = 0; l < LL; l++) {
        ln_kernel<<<MM, 256>>>(X, attn_norm_g + (size_t)l * DD, nullptr, XNh, XNl, 0);  // launch 5 (l=0)
        run_gemm(XNh, XNl, WqTh + (size_t)l * 512 * DD, WqTl + (size_t)l * 512 * DD,
                 nullptr, Q, nullptr, nullptr, MM, 512, DD, 0);                          // launch 6 (l=0) <- ncu
        run_gemm(XNh, XNl, WkvTh + (size_t)l * 128 * DD, WkvTl + (size_t)l * 128 * DD,
                 bkv + l * 128, KV, nullptr, nullptr, MM, 128, DD, 0);
        qpost_kernel<<<(MM * HH * 32 + 255) / 256, 256>>>();
        kvpost_kernel<<<(BB * NKV * 32 + 255) / 256, 256>>>(null_kv + (size_t)l * 128);
        attn_kernel<<<(BB * HH * NN * 32 + 255) / 256, 256>>>();
        run_gemm(Oh, Ol, WoTh + (size_t)l * DD * 512, WoTl + (size_t)l * DD * 512,
                 nullptr, T, nullptr, nullptr, MM, DD, 512, 0);
        ln_kernel<<<MM, 256>>>(T, out_norm_g + (size_t)l * DD, X, nullptr, nullptr, 1);
        ln_kernel<<<MM, 256>>>(X, ff_norm_g + (size_t)l * DD, nullptr, XNh, XNl, 0);
        run_gemm(XNh, XNl, W1Th + (size_t)l * 2 * FFD * DD, W1Tl + (size_t)l * 2 * FFD * DD,
                 nullptr, nullptr, AGh, AGl, MM, 2 * FFD, DD, 2);   // fused GLU epilogue
        run_gemm(AGh, AGl, W2Th + (size_t)l * DD * FFD, W2Tl + (size_t)l * DD * FFD,
                 nullptr, X, nullptr, nullptr, MM, DD, FFD, 1);
    }

    ln_kernel<<<MM, 256>>>(X, final_norm_g, nullptr, XNh, XNl, 2);
    run_gemm(XNh, XNl, WpTh, WpTl, nullptr, out, nullptr, nullptr, MM, DD, DD, 0);
}

// round 8
// speedup vs baseline: 3.3540x; 1.2538x over previous
#include <cuda_runtime.h>
#include <cuda_fp16.h>
#include <math.h>
#include <float.h>
#include <stdint.h>

#define BB   8
#define NN   515
#define DD   1024
#define HH   8
#define LL   4
#define FFD  4096
#define NKV  516
#define MM   (BB*NN)
#define EPSL 1e-5f

// ---------------- scratch ----------------
__device__ float g_X [MM*DD];
__device__ float g_Q [MM*512];
__device__ float g_KV[MM*128];
__device__ float g_K [BB*NKV*64];
__device__ float g_V [BB*NKV*64];
__device__ float g_T [MM*DD];
__device__ float g_bias[HH*NN*NKV];
__device__ float g_cos[NN*16];
__device__ float g_sin[NN*16];
__device__ __half g_XNh[MM*DD],  g_XNl[MM*DD];
__device__ __half g_Oh [MM*512], g_Ol [MM*512];
__device__ __half g_AGh[(size_t)MM*FFD], g_AGl[(size_t)MM*FFD];
__device__ __half g_WqT [LL*512*DD];
__device__ __half g_WkvT[LL*128*DD];
__device__ __half g_WoT [LL*DD*512];
__device__ __half g_Wff1T[(size_t)LL*2*FFD*DD];
__device__ __half g_Wff2T[(size_t)LL*DD*FFD];
__device__ __half g_WprojT[DD*DD];

// ---------------- small helpers ----------------
__device__ __forceinline__ uint32_t smem_u32(const void* p) {
    uint32_t a;
    asm("{ .reg .u64 t; cvta.to.shared.u64 t, %1; cvt.u32.u64 %0, t; }" : "=r"(a) : "l"(p));
    return a;
}
__device__ __forceinline__ void cp16(uint32_t dst, const void* src, bool pred) {
    int sz = pred ? 16 : 0;
    asm volatile("cp.async.cg.shared.global [%0], [%1], 16, %2;\n" :: "r"(dst), "l"(src), "r"(sz));
}
__device__ __forceinline__ void cp_commit() {
    asm volatile("cp.async.commit_group;\n" ::: "memory");
}
template<int N>
__device__ __forceinline__ void cp_wait() {
    asm volatile("cp.async.wait_group %0;\n" :: "n"(N) : "memory");
}
__device__ __forceinline__ void ldsm4(uint32_t* r, uint32_t addr) {
    asm volatile("ldmatrix.sync.aligned.m8n8.x4.shared.b16 {%0,%1,%2,%3}, [%4];"
                 : "=r"(r[0]), "=r"(r[1]), "=r"(r[2]), "=r"(r[3]) : "r"(addr));
}
__device__ __forceinline__ void mma_f16(float* c, const uint32_t* a, const uint32_t* b) {
    asm volatile(
        "mma.sync.aligned.m16n8k16.row.col.f32.f16.f16.f32 "
        "{%0,%1,%2,%3}, {%4,%5,%6,%7}, {%8,%9}, {%0,%1,%2,%3};"
        : "+f"(c[0]), "+f"(c[1]), "+f"(c[2]), "+f"(c[3])
        : "r"(a[0]), "r"(a[1]), "r"(a[2]), "r"(a[3]), "r"(b[0]), "r"(b[1]));
}

// ===== mma.sync 2-term fp16-split GEMM: C[M,N] = A[M,K] @ B[N,K]^T ========
// A given as fp16 hi/lo pair (exact to 2^-24); B single fp16 (weights).
// D = Ah*B + Al*B, fp32 accum.
// mode 0: C = result (+bias) ; 1: C += result ; 2: GLU epilogue (interleaved
// a/g columns -> out = a*silu(g), split fp16, width N/2).
#define TILE_HB   (128*40*2)            // 10240 B per tile
#define STAGE_B   (3*TILE_HB)           // Ah, Al, Bh
#define SMEM_TOT  (2*STAGE_B)           // 61440 B

__global__ __launch_bounds__(256, 2)
void bgemm_kernel(const __half* __restrict__ Ah, const __half* __restrict__ Al,
                  const __half* __restrict__ Bh,
                  const float* __restrict__ bias, float* __restrict__ C,
                  __half* __restrict__ outh, __half* __restrict__ outl,
                  int M, int N, int K, int mode)
{
    extern __shared__ char smem[];
    const uint32_t sbase = smem_u32(smem);

    const int tid  = threadIdx.x;
    const int lane = tid & 31;
    const int warp = tid >> 5;
    const int warp_row = (warp & 1) * 64;
    const int warp_col = (warp >> 1) * 32;
    const int block_row = blockIdx.y * 128;
    const int block_col = blockIdx.x * 128;
    const int KC = K >> 5;

    const int g0row = tid >> 2;
    const int g0c   = (tid & 3) * 8;
    const int g1row = (tid + 256) >> 2;
    const int g1c   = g0c;

    const int aRow  = (lane & 15);
    const int aColH = (lane >> 4) << 3;
    const int bRow  = ((lane >> 4) << 3) + (lane & 7);
    const int bColH = ((lane >> 3) & 1) << 3;

    float acc[4][4][4];
    #pragma unroll
    for (int a = 0; a < 4; a++)
        #pragma unroll
        for (int b = 0; b < 4; b++)
            #pragma unroll
            for (int c = 0; c < 4; c++) acc[a][b][c] = 0.f;

    auto load_chunk = [&](int s, int k0) {
        const uint32_t st = sbase + s * STAGE_B;
        {
            int r0 = block_row + g0row, r1 = block_row + g1row;
            bool p0 = r0 < M, p1 = r1 < M;
            cp16(st + (g0row * 40 + g0c) * 2, Ah + (size_t)r0 * K + k0 + g0c, p0);
            cp16(st + (g1row * 40 + g1c) * 2, Ah + (size_t)r1 * K + k0 + g1c, p1);
            cp16(st + TILE_HB + (g0row * 40 + g0c) * 2, Al + (size_t)r0 * K + k0 + g0c, p0);
            cp16(st + TILE_HB + (g1row * 40 + g1c) * 2, Al + (size_t)r1 * K + k0 + g1c, p1);
        }
        {
            int r0 = block_col + g0row, r1 = block_col + g1row;
            cp16(st + 2 * TILE_HB + (g0row * 40 + g0c) * 2, Bh + (size_t)r0 * K + k0 + g0c, true);
            cp16(st + 2 * TILE_HB + (g1row * 40 + g1c) * 2, Bh + (size_t)r1 * K + k0 + g1c, true);
        }
        cp_commit();
    };

    load_chunk(0, 0);

    for (int c = 0; c < KC; ++c) {
        const int s = c & 1;
        if (c + 1 < KC) {
            load_chunk(s ^ 1, (c + 1) << 5);
            cp_wait<1>();
        } else {
            cp_wait<0>();
        }
        __syncthreads();

        const uint32_t st = sbase + s * STAGE_B;
        #pragma unroll
        for (int ks = 0; ks < 2; ks++) {
            const int k0s = ks << 4;
            uint32_t ah[4][4], al[4][4], bh[2][4];
            #pragma unroll
            for (int mt = 0; mt < 4; mt++) {
                const uint32_t addr = st + ((warp_row + mt * 16 + aRow) * 40 + k0s + aColH) * 2;
                ldsm4(ah[mt], addr);
                ldsm4(al[mt], addr + TILE_HB);
            }
            #pragma unroll
            for (int np = 0; np < 2; np++) {
                const uint32_t addr = st + 2 * TILE_HB +
                    ((warp_col + np * 16 + bRow) * 40 + k0s + bColH) * 2;
                ldsm4(bh[np], addr);
            }
            #pragma unroll
            for (int mt = 0; mt < 4; mt++)
                #pragma unroll
                for (int nt = 0; nt < 4; nt++)
                    mma_f16(acc[mt][nt], ah[mt], &bh[nt >> 1][(nt & 1) * 2]);
            #pragma unroll
            for (int mt = 0; mt < 4; mt++)
                #pragma unroll
                for (int nt = 0; nt < 4; nt++)
                    mma_f16(acc[mt][nt], al[mt], &bh[nt >> 1][(nt & 1) * 2]);
        }
        __syncthreads();
    }

    // ---- epilogue
    const int gid = lane >> 2;
    const int tig = lane & 3;
    #pragma unroll
    for (int mt = 0; mt < 4; mt++) {
        int r0 = block_row + warp_row + mt * 16 + gid;
        #pragma unroll
        for (int half = 0; half < 2; half++) {
            int r = r0 + half * 8;
            if (r >= M) continue;
            #pragma unroll
            for (int nt = 0; nt < 4; nt++) {
                int col = block_col + warp_col + nt * 8 + 2 * tig;
                float v0 = acc[mt][nt][half * 2 + 0];
                float v1 = acc[mt][nt][half * 2 + 1];
                if (mode == 2) {
                    float v = v0 * v1 / (1.f + __expf(-v1));
                    __half h = __float2half_rn(v);
                    size_t o = (size_t)r * (N >> 1) + (col >> 1);
                    outh[o] = h;
                    outl[o] = __float2half_rn(v - __half2float(h));
                } else {
                    if (bias) { v0 += bias[col]; v1 += bias[col + 1]; }
                    float* cp = C + (size_t)r * N + col;
                    if (mode == 1) { cp[0] += v0; cp[1] += v1; }
                    else           { cp[0]  = v0; cp[1]  = v1; }
                }
            }
        }
    }
}

// -------- fused weight transpose (fp16, one launch, tight grid) ------------
// W[K][N] -> T[N][K] fp16. glu permutes source cols (a/g interleave).
struct WDesc { const float* W; __half* Th; int K; int N; int glu; };
struct WTable { WDesc d[21]; int off[22]; };

__global__ void wsplit_all_kernel(WTable tab) {
    const int bid = blockIdx.x;
    int wi = 0;
    while (bid >= tab.off[wi + 1]) wi++;
    const WDesc w = tab.d[wi];
    const int t = bid - tab.off[wi];
    const int tilesN = w.N >> 5;
    const int nb = (t % tilesN) * 32;
    const int kb = (t / tilesN) * 32;
    __shared__ float sm[32][33];
    const int x = threadIdx.x, y = threadIdx.y;
    const int n0 = nb + x;
    const int sc = w.glu ? ((n0 & 1) * FFD + (n0 >> 1)) : n0;
    #pragma unroll
    for (int j = 0; j < 32; j += 8)
        sm[y + j][x] = w.W[(size_t)(kb + y + j) * w.N + sc];
    __syncthreads();
    #pragma unroll
    for (int j = 0; j < 32; j += 8)
        w.Th[(size_t)(nb + y + j) * w.K + kb + x] = __float2half_rn(sm[x][y + j]);
}

// ---------------- reductions ----------------
__device__ __forceinline__ float warpReduceSum(float v) {
    #pragma unroll
    for (int o = 16; o > 0; o >>= 1) v += __shfl_xor_sync(0xffffffffu, v, o);
    return v;
}
__device__ __forceinline__ float warpReduceMax(float v) {
    #pragma unroll
    for (int o = 16; o > 0; o >>= 1) v = fmaxf(v, __shfl_xor_sync(0xffffffffu, v, o));
    return v;
}
__device__ __forceinline__ float blockReduceSum(float v) {
    __shared__ float sh[8];
    int lane = threadIdx.x & 31, w = threadIdx.x >> 5;
    v = warpReduceSum(v);
    __syncthreads();
    if (lane == 0) sh[w] = v;
    __syncthreads();
    if (w == 0) {
        float t = (lane < 8) ? sh[lane] : 0.f;
        t = warpReduceSum(t);
        if (lane == 0) sh[0] = t;
    }
    __syncthreads();
    return sh[0];
}
__device__ __forceinline__ float blockReduceMax(float v) {
    __shared__ float sh[8];
    int lane = threadIdx.x & 31, w = threadIdx.x >> 5;
    v = warpReduceMax(v);
    __syncthreads();
    if (lane == 0) sh[w] = v;
    __syncthreads();
    if (w == 0) {
        float t = (lane < 8) ? sh[lane] : -FLT_MAX;
        t = warpReduceMax(t);
        if (lane == 0) sh[0] = t;
    }
    __syncthreads();
    return sh[0];
}

// -------- LayerNorm ---------------------------------------------------------
// mode 0: split(LN(in)*g) -> outh/outl
// mode 1: outf = resid + LN(in)*g
// mode 2: stable LN, split -> outh/outl
__global__ __launch_bounds__(256)
void ln_kernel(const float* __restrict__ in, const float* __restrict__ resid,
               const float* __restrict__ g,
               float* __restrict__ outf, __half* __restrict__ outh,
               __half* __restrict__ outl, int mode)
{
    const int row = blockIdx.x;
    const float* xr = in + (size_t)row * DD;
    const int t = threadIdx.x;
    float v[4];
    #pragma unroll
    for (int i = 0; i < 4; i++) v[i] = xr[t + i * 256];
    if (mode == 2) {
        float lm = -FLT_MAX;
        #pragma unroll
        for (int i = 0; i < 4; i++) lm = fmaxf(lm, v[i]);
        float inv = 1.f / blockReduceMax(lm);
        #pragma unroll
        for (int i = 0; i < 4; i++) v[i] *= inv;
    }
    float s = 0.f;
    #pragma unroll
    for (int i = 0; i < 4; i++) s += v[i];
    float mean = blockReduceSum(s) * (1.f / DD);
    float vs = 0.f;
    #pragma unroll
    for (int i = 0; i < 4; i++) { float d = v[i] - mean; vs += d * d; }
    float rstd = rsqrtf(blockReduceSum(vs) * (1.f / DD) + EPSL);
    #pragma unroll
    for (int i = 0; i < 4; i++) {
        int c = t + i * 256;
        float y = (v[i] - mean) * rstd * g[c];
        size_t idx = (size_t)row * DD + c;
        if (mode == 1) {
            outf[idx] = resid[idx] + y;
        } else {
            __half h = __float2half_rn(y);
            outh[idx] = h;
            outl[idx] = __float2half_rn(y - __half2float(h));
        }
    }
}

// ---------------- precompute: rope tables + rel-pos bias (fused) -----------
__global__ void precompute_kernel(const float* __restrict__ emb) {
    int idx = blockIdx.x * blockDim.x + threadIdx.x;
    if (idx < NN * 16) {
        int p = idx >> 4, i = idx & 15;
        float fr = (float)p * powf(10000.f, -(float)(2 * i) / 32.f);
        g_cos[idx] = cosf(fr);
        g_sin[idx] = sinf(fr);
    }
    if (idx >= NN * NKV) return;
    int i = idx / NKV, j = idx % NKV;
    int nn = max(i - j, 0);
    int bucket;
    if (nn < 16) bucket = nn;
    else {
        int vl = 16 + (int)(logf((float)nn * (1.f / 16.f)) / logf(8.f) * 16.f);
        bucket = min(vl, 31);
    }
    #pragma unroll
    for (int h = 0; h < HH; h++)
        g_bias[((size_t)h * NN + i) * NKV + j] = emb[bucket * HH + h];
}

// ---------------- q/kv post ----------------
__global__ __launch_bounds__(256)
void qpost_kernel() {
    int gw   = (blockIdx.x * blockDim.x + threadIdx.x) >> 5;
    int lane = threadIdx.x & 31;
    if (gw >= MM * HH) return;
    int m = gw / HH, h = gw % HH;
    int pos = m % NN;
    float* qp = g_Q + (size_t)m * 512 + h * 64;
    float q0 = qp[lane], q1 = qp[lane + 32];
    float c = g_cos[pos * 16 + (lane >> 1)];
    float s = g_sin[pos * 16 + (lane >> 1)];
    float part = __shfl_xor_sync(0xffffffffu, q0, 1);
    q0 = (lane & 1) ? fmaf(q0, c, part * s) : fmaf(q0, c, -part * s);
    float inv = 4.f * rsqrtf(warpReduceSum(q0 * q0 + q1 * q1));
    qp[lane] = q0 * inv;
    qp[lane + 32] = q1 * inv;
}
__global__ __launch_bounds__(256)
void kvpost_kernel(const float* __restrict__ nullkv) {
    int gw   = (blockIdx.x * blockDim.x + threadIdx.x) >> 5;
    int lane = threadIdx.x & 31;
    if (gw >= BB * NKV) return;
    int b = gw / NKV, j = gw % NKV;
    float k0, k1, v0, v1;
    if (j == 0) {
        k0 = nullkv[lane];      k1 = nullkv[lane + 32];
        v0 = nullkv[64 + lane]; v1 = nullkv[96 + lane];
    } else {
        int pos = j - 1;
        const float* kv = g_KV + ((size_t)(b * NN + pos)) * 128;
        k0 = kv[lane];      k1 = kv[lane + 32];
        v0 = kv[64 + lane]; v1 = kv[96 + lane];
        float c = g_cos[pos * 16 + (lane >> 1)];
        float s = g_sin[pos * 16 + (lane >> 1)];
        float part = __shfl_xor_sync(0xffffffffu, k0, 1);
        k0 = (lane & 1) ? fmaf(k0, c, part * s) : fmaf(k0, c, -part * s);
    }
    float inv = 4.f * rsqrtf(warpReduceSum(k0 * k0 + k1 * k1));
    size_t o = ((size_t)(b * NKV + j)) * 64;
    g_K[o + lane] = k0 * inv;  g_K[o + lane + 32] = k1 * inv;
    g_V[o + lane] = v0;        g_V[o + lane + 32] = v1;
}

// -------- attention: one warp per (b,h,i); fp16-split output ---------------
__global__ __launch_bounds__(256)
void attn_kernel() {
    int gw   = (blockIdx.x * blockDim.x + threadIdx.x) >> 5;
    int lane = threadIdx.x & 31;
    if (gw >= BB * HH * NN) return;
    int i  = gw % NN;
    int bh = gw / NN;
    int h  = bh % HH, b = bh / HH;

    const float* qp = g_Q + ((size_t)(b * NN + i)) * 512 + h * 64;
    float q0 = qp[lane], q1 = qp[lane + 32];
    const float* Kb = g_K + (size_t)b * NKV * 64;
    const float* Vb = g_V + (size_t)b * NKV * 64;
    const float* bp = g_bias + ((size_t)h * NN + i) * NKV;

    float m = -1e30f, lsum = 0.f, o0 = 0.f, o1 = 0.f;
    int jmax = i + 1;
    for (int j = 0; j <= jmax; j++) {
        const float* kp = Kb + (size_t)j * 64;
        float d = q0 * kp[lane] + q1 * kp[lane + 32];
        #pragma unroll
        for (int off = 16; off > 0; off >>= 1)
            d += __shfl_xor_sync(0xffffffffu, d, off);
        float s  = d + bp[j];
        float mn = fmaxf(m, s);
        float corr = __expf(m - mn);
        float w    = __expf(s - mn);
        lsum = lsum * corr + w;
        o0 = o0 * corr + w * Vb[(size_t)j * 64 + lane];
        o1 = o1 * corr + w * Vb[(size_t)j * 64 + lane + 32];
        m = mn;
    }
    float inv = 1.f / lsum;
    o0 *= inv; o1 *= inv;
    size_t op = ((size_t)(b * NN + i)) * 512 + h * 64;
    __half h0 = __float2half_rn(o0);
    __half h1 = __float2half_rn(o1);
    g_Oh[op + lane] = h0;       g_Ol[op + lane]      = __float2half_rn(o0 - __half2float(h0));
    g_Oh[op + lane + 32] = h1;  g_Ol[op + lane + 32] = __float2half_rn(o1 - __half2float(h1));
}

// ---------------- host orchestration --------------------------------------
static inline void run_gemm(const __half* Ah, const __half* Al, const __half* Bh,
                            const float* bias, float* C,
                            __half* outh, __half* outl,
                            int M, int N, int K, int mode) {
    dim3 grid(N / 128, (M + 127) / 128);
    bgemm_kernel<<<grid, 256, SMEM_TOT>>>(Ah, Al, Bh, bias, C, outh, outl, M, N, K, mode);
}

extern "C" void kernel_launch(void* const* d_in, const int* in_sizes, int n_in,
                              void* d_out, int out_size) {
    (void)in_sizes; (void)n_in; (void)out_size;
    const float* x            = (const float*)d_in[0];
    const float* attn_norm_g  = (const float*)d_in[1];
    const float* Wq           = (const float*)d_in[2];
    const float* Wkv          = (const float*)d_in[3];
    const float* bkv          = (const float*)d_in[4];
    const float* null_kv      = (const float*)d_in[5];
    const float* Wo           = (const float*)d_in[6];
    const float* out_norm_g   = (const float*)d_in[7];
    const float* ff_norm_g    = (const float*)d_in[8];
    const float* Wff1         = (const float*)d_in[9];
    const float* Wff2         = (const float*)d_in[10];
    const float* relpos       = (const float*)d_in[11];
    const float* final_norm_g = (const float*)d_in[12];
    const float* Wproj        = (const float*)d_in[13];
    float* out = (float*)d_out;

    cudaFuncSetAttribute(bgemm_kernel, cudaFuncAttributeMaxDynamicSharedMemorySize, SMEM_TOT);

    float *X, *Q, *KV, *T;
    __half *XNh, *XNl, *Oh, *Ol, *AGh, *AGl;
    __half *WqT, *WkvT, *WoT, *W1T, *W2T, *WpT;
    cudaGetSymbolAddress((void**)&X,  g_X);
    cudaGetSymbolAddress((void**)&Q,  g_Q);
    cudaGetSymbolAddress((void**)&KV, g_KV);
    cudaGetSymbolAddress((void**)&T,  g_T);
    cudaGetSymbolAddress((void**)&XNh, g_XNh); cudaGetSymbolAddress((void**)&XNl, g_XNl);
    cudaGetSymbolAddress((void**)&Oh,  g_Oh);  cudaGetSymbolAddress((void**)&Ol,  g_Ol);
    cudaGetSymbolAddress((void**)&AGh, g_AGh); cudaGetSymbolAddress((void**)&AGl, g_AGl);
    cudaGetSymbolAddress((void**)&WqT, g_WqT);
    cudaGetSymbolAddress((void**)&WkvT, g_WkvT);
    cudaGetSymbolAddress((void**)&WoT, g_WoT);
    cudaGetSymbolAddress((void**)&W1T, g_Wff1T);
    cudaGetSymbolAddress((void**)&W2T, g_Wff2T);
    cudaGetSymbolAddress((void**)&WpT, g_WprojT);

    // launch 1: precompute (rope + bias fused)
    precompute_kernel<<<(NN * NKV + 255) / 256, 256>>>(relpos);

    // launch 2: fused weight transpose (tight grid)
    WTable tab;
    int di = 0;
    for (int l = 0; l < LL; l++) {
        tab.d[di++] = { Wq   + (size_t)l * DD * 512,     WqT + (size_t)l * 512 * DD,     DD,  512,     0 };
        tab.d[di++] = { Wkv  + (size_t)l * DD * 128,     WkvT + (size_t)l * 128 * DD,    DD,  128,     0 };
        tab.d[di++] = { Wo   + (size_t)l * 512 * DD,     WoT + (size_t)l * DD * 512,     512, DD,      0 };
        tab.d[di++] = { Wff1 + (size_t)l * DD * 2 * FFD, W1T + (size_t)l * 2 * FFD * DD, DD,  2 * FFD, 1 };
        tab.d[di++] = { Wff2 + (size_t)l * FFD * DD,     W2T + (size_t)l * DD * FFD,     FFD, DD,      0 };
    }
    tab.d[di++] = { Wproj, WpT, DD, DD, 0 };
    tab.off[0] = 0;
    for (int i = 0; i < 21; i++)
        tab.off[i + 1] = tab.off[i] + (tab.d[i].N >> 5) * (tab.d[i].K >> 5);
    wsplit_all_kernel<<<tab.off[21], dim3(32, 8)>>>(tab);

    for (int l = 0; l < LL; l++) {
        const float* xin = (l == 0) ? x : X;
        // launch 3 (l=0): attn LN
        ln_kernel<<<MM, 256>>>(xin, nullptr, attn_norm_g + (size_t)l * DD, nullptr, XNh, XNl, 0);
        // launch 4 (l=0): first bgemm  <- ncu capture slot
        run_gemm(XNh, XNl, WqT + (size_t)l * 512 * DD, nullptr, Q, nullptr, nullptr, MM, 512, DD, 0);
        run_gemm(XNh, XNl, WkvT + (size_t)l * 128 * DD, bkv + l * 128, KV, nullptr, nullptr, MM, 128, DD, 0);
        qpost_kernel<<<(MM * HH * 32 + 255) / 256, 256>>>();
        kvpost_kernel<<<(BB * NKV * 32 + 255) / 256, 256>>>(null_kv + (size_t)l * 128);
        attn_kernel<<<(BB * HH * NN * 32 + 255) / 256, 256>>>();
        run_gemm(Oh, Ol, WoT + (size_t)l * DD * 512, nullptr, T, nullptr, nullptr, MM, DD, 512, 0);
        ln_kernel<<<MM, 256>>>(T, xin, out_norm_g + (size_t)l * DD, X, nullptr, nullptr, 1);
        ln_kernel<<<MM, 256>>>(X, nullptr, ff_norm_g + (size_t)l * DD, nullptr, XNh, XNl, 0);
        run_gemm(XNh, XNl, W1T + (size_t)l * 2 * FFD * DD, nullptr, nullptr, AGh, AGl, MM, 2 * FFD, DD, 2);
        run_gemm(AGh, AGl, W2T + (size_t)l * DD * FFD, nullptr, X, nullptr, nullptr, MM, DD, FFD, 1);
    }

    ln_kernel<<<MM, 256>>>(X, nullptr, final_norm_g, nullptr, XNh, XNl, 2);
    run_gemm(XNh, XNl, WpT, nullptr, out, nullptr, nullptr, MM, DD, DD, 0);
}

// round 9
// speedup vs baseline: 3.8478x; 1.1472x over previous
#include <cuda_runtime.h>
#include <cuda_fp16.h>
#include <math.h>
#include <float.h>
#include <stdint.h>

#define BB   8
#define NN   515
#define DD   1024
#define HH   8
#define LL   4
#define FFD  4096
#define NKV  516
#define MM   (BB*NN)
#define KTP  552                 // padded Kt row length (>= 515+32)
#define EPSL 1e-5f

// ---------------- scratch ----------------
__device__ float g_X  [MM*DD];
__device__ float g_QKV[MM*640];                // q (0..511) | kv (512..639)
__device__ float g_Kt [BB*64*KTP];             // [b][d][j], zero-padded
__device__ float g_V  [(BB*NKV + 32)*64];      // padded rows
__device__ float g_T  [MM*DD];
__device__ float g_bias[HH*NN*NKV + 64];       // padded
__device__ float g_bqkv[LL*640];               // 0s | bkv
__device__ float g_cos[NN*16];
__device__ float g_sin[NN*16];
__device__ __half g_XNh[MM*DD],  g_XNl[MM*DD];
__device__ __half g_Oh [MM*512], g_Ol [MM*512];
__device__ __half g_AGh[(size_t)MM*FFD], g_AGl[(size_t)MM*FFD];
__device__ __half g_WqkvT[LL*640*DD];
__device__ __half g_WoT  [LL*DD*512];
__device__ __half g_Wff1T[(size_t)LL*2*FFD*DD];
__device__ __half g_Wff2T[(size_t)LL*DD*FFD];
__device__ __half g_WprojT[DD*DD];

// ---------------- small helpers ----------------
__device__ __forceinline__ uint32_t smem_u32(const void* p) {
    uint32_t a;
    asm("{ .reg .u64 t; cvta.to.shared.u64 t, %1; cvt.u32.u64 %0, t; }" : "=r"(a) : "l"(p));
    return a;
}
__device__ __forceinline__ void cp16(uint32_t dst, const void* src, bool pred) {
    int sz = pred ? 16 : 0;
    asm volatile("cp.async.cg.shared.global [%0], [%1], 16, %2;\n" :: "r"(dst), "l"(src), "r"(sz));
}
__device__ __forceinline__ void cp_commit() {
    asm volatile("cp.async.commit_group;\n" ::: "memory");
}
template<int N>
__device__ __forceinline__ void cp_wait() {
    asm volatile("cp.async.wait_group %0;\n" :: "n"(N) : "memory");
}
__device__ __forceinline__ void ldsm4(uint32_t* r, uint32_t addr) {
    asm volatile("ldmatrix.sync.aligned.m8n8.x4.shared.b16 {%0,%1,%2,%3}, [%4];"
                 : "=r"(r[0]), "=r"(r[1]), "=r"(r[2]), "=r"(r[3]) : "r"(addr));
}
__device__ __forceinline__ void mma_f16(float* c, const uint32_t* a, const uint32_t* b) {
    asm volatile(
        "mma.sync.aligned.m16n8k16.row.col.f32.f16.f16.f32 "
        "{%0,%1,%2,%3}, {%4,%5,%6,%7}, {%8,%9}, {%0,%1,%2,%3};"
        : "+f"(c[0]), "+f"(c[1]), "+f"(c[2]), "+f"(c[3])
        : "r"(a[0]), "r"(a[1]), "r"(a[2]), "r"(a[3]), "r"(b[0]), "r"(b[1]));
}

// ===== mma.sync 2-term fp16-split GEMM (identical math to round 8) ========
#define TILE_HB   (128*40*2)
#define STAGE_B   (3*TILE_HB)
#define SMEM_TOT  (2*STAGE_B)

__global__ __launch_bounds__(256, 2)
void bgemm_kernel(const __half* __restrict__ Ah, const __half* __restrict__ Al,
                  const __half* __restrict__ Bh,
                  const float* __restrict__ bias, float* __restrict__ C,
                  __half* __restrict__ outh, __half* __restrict__ outl,
                  int M, int N, int K, int mode)
{
    extern __shared__ char smem[];
    const uint32_t sbase = smem_u32(smem);

    const int tid  = threadIdx.x;
    const int lane = tid & 31;
    const int warp = tid >> 5;
    const int warp_row = (warp & 1) * 64;
    const int warp_col = (warp >> 1) * 32;
    const int block_row = blockIdx.y * 128;
    const int block_col = blockIdx.x * 128;
    const int KC = K >> 5;

    const int g0row = tid >> 2;
    const int g0c   = (tid & 3) * 8;
    const int g1row = (tid + 256) >> 2;
    const int g1c   = g0c;

    const int aRow  = (lane & 15);
    const int aColH = (lane >> 4) << 3;
    const int bRow  = ((lane >> 4) << 3) + (lane & 7);
    const int bColH = ((lane >> 3) & 1) << 3;

    float acc[4][4][4];
    #pragma unroll
    for (int a = 0; a < 4; a++)
        #pragma unroll
        for (int b = 0; b < 4; b++)
            #pragma unroll
            for (int c = 0; c < 4; c++) acc[a][b][c] = 0.f;

    auto load_chunk = [&](int s, int k0) {
        const uint32_t st = sbase + s * STAGE_B;
        {
            int r0 = block_row + g0row, r1 = block_row + g1row;
            bool p0 = r0 < M, p1 = r1 < M;
            cp16(st + (g0row * 40 + g0c) * 2, Ah + (size_t)r0 * K + k0 + g0c, p0);
            cp16(st + (g1row * 40 + g1c) * 2, Ah + (size_t)r1 * K + k0 + g1c, p1);
            cp16(st + TILE_HB + (g0row * 40 + g0c) * 2, Al + (size_t)r0 * K + k0 + g0c, p0);
            cp16(st + TILE_HB + (g1row * 40 + g1c) * 2, Al + (size_t)r1 * K + k0 + g1c, p1);
        }
        {
            int r0 = block_col + g0row, r1 = block_col + g1row;
            cp16(st + 2 * TILE_HB + (g0row * 40 + g0c) * 2, Bh + (size_t)r0 * K + k0 + g0c, true);
            cp16(st + 2 * TILE_HB + (g1row * 40 + g1c) * 2, Bh + (size_t)r1 * K + k0 + g1c, true);
        }
        cp_commit();
    };

    load_chunk(0, 0);

    for (int c = 0; c < KC; ++c) {
        const int s = c & 1;
        if (c + 1 < KC) {
            load_chunk(s ^ 1, (c + 1) << 5);
            cp_wait<1>();
        } else {
            cp_wait<0>();
        }
        __syncthreads();

        const uint32_t st = sbase + s * STAGE_B;
        #pragma unroll
        for (int ks = 0; ks < 2; ks++) {
            const int k0s = ks << 4;
            uint32_t ah[4][4], al[4][4], bh[2][4];
            #pragma unroll
            for (int mt = 0; mt < 4; mt++) {
                const uint32_t addr = st + ((warp_row + mt * 16 + aRow) * 40 + k0s + aColH) * 2;
                ldsm4(ah[mt], addr);
                ldsm4(al[mt], addr + TILE_HB);
            }
            #pragma unroll
            for (int np = 0; np < 2; np++) {
                const uint32_t addr = st + 2 * TILE_HB +
                    ((warp_col + np * 16 + bRow) * 40 + k0s + bColH) * 2;
                ldsm4(bh[np], addr);
            }
            #pragma unroll
            for (int mt = 0; mt < 4; mt++)
                #pragma unroll
                for (int nt = 0; nt < 4; nt++)
                    mma_f16(acc[mt][nt], ah[mt], &bh[nt >> 1][(nt & 1) * 2]);
            #pragma unroll
            for (int mt = 0; mt < 4; mt++)
                #pragma unroll
                for (int nt = 0; nt < 4; nt++)
                    mma_f16(acc[mt][nt], al[mt], &bh[nt >> 1][(nt & 1) * 2]);
        }
        __syncthreads();
    }

    const int gid = lane >> 2;
    const int tig = lane & 3;
    #pragma unroll
    for (int mt = 0; mt < 4; mt++) {
        int r0 = block_row + warp_row + mt * 16 + gid;
        #pragma unroll
        for (int half = 0; half < 2; half++) {
            int r = r0 + half * 8;
            if (r >= M) continue;
            #pragma unroll
            for (int nt = 0; nt < 4; nt++) {
                int col = block_col + warp_col + nt * 8 + 2 * tig;
                float v0 = acc[mt][nt][half * 2 + 0];
                float v1 = acc[mt][nt][half * 2 + 1];
                if (mode == 2) {
                    float v = v0 * v1 / (1.f + __expf(-v1));
                    __half h = __float2half_rn(v);
                    size_t o = (size_t)r * (N >> 1) + (col >> 1);
                    outh[o] = h;
                    outl[o] = __float2half_rn(v - __half2float(h));
                } else {
                    if (bias) { v0 += bias[col]; v1 += bias[col + 1]; }
                    float* cp = C + (size_t)r * N + col;
                    if (mode == 1) { cp[0] += v0; cp[1] += v1; }
                    else           { cp[0]  = v0; cp[1]  = v1; }
                }
            }
        }
    }
}

// -------- fused weight transpose (fp16, one launch, tight grid) ------------
struct WDesc { const float* W; __half* Th; int K; int N; int glu; };
struct WTable { WDesc d[21]; int off[22]; };

__global__ void wsplit_all_kernel(WTable tab) {
    const int bid = blockIdx.x;
    int wi = 0;
    while (bid >= tab.off[wi + 1]) wi++;
    const WDesc w = tab.d[wi];
    const int t = bid - tab.off[wi];
    const int tilesN = w.N >> 5;
    const int nb = (t % tilesN) * 32;
    const int kb = (t / tilesN) * 32;
    __shared__ float sm[32][33];
    const int x = threadIdx.x, y = threadIdx.y;
    const int n0 = nb + x;
    const int sc = w.glu ? ((n0 & 1) * FFD + (n0 >> 1)) : n0;
    #pragma unroll
    for (int j = 0; j < 32; j += 8)
        sm[y + j][x] = w.W[(size_t)(kb + y + j) * w.N + sc];
    __syncthreads();
    #pragma unroll
    for (int j = 0; j < 32; j += 8)
        w.Th[(size_t)(nb + y + j) * w.K + kb + x] = __float2half_rn(sm[x][y + j]);
}

// ---------------- reductions ----------------
__device__ __forceinline__ float warpReduceSum(float v) {
    #pragma unroll
    for (int o = 16; o > 0; o >>= 1) v += __shfl_xor_sync(0xffffffffu, v, o);
    return v;
}
__device__ __forceinline__ float warpReduceMax(float v) {
    #pragma unroll
    for (int o = 16; o > 0; o >>= 1) v = fmaxf(v, __shfl_xor_sync(0xffffffffu, v, o));
    return v;
}
__device__ __forceinline__ float blockReduceSum(float v) {
    __shared__ float sh[8];
    int lane = threadIdx.x & 31, w = threadIdx.x >> 5;
    v = warpReduceSum(v);
    __syncthreads();
    if (lane == 0) sh[w] = v;
    __syncthreads();
    if (w == 0) {
        float t = (lane < 8) ? sh[lane] : 0.f;
        t = warpReduceSum(t);
        if (lane == 0) sh[0] = t;
    }
    __syncthreads();
    return sh[0];
}
__device__ __forceinline__ float blockReduceMax(float v) {
    __shared__ float sh[8];
    int lane = threadIdx.x & 31, w = threadIdx.x >> 5;
    v = warpReduceMax(v);
    __syncthreads();
    if (lane == 0) sh[w] = v;
    __syncthreads();
    if (w == 0) {
        float t = (lane < 8) ? sh[lane] : -FLT_MAX;
        t = warpReduceMax(t);
        if (lane == 0) sh[0] = t;
    }
    __syncthreads();
    return sh[0];
}

// -------- LayerNorm: mode 0 split(LN(in)*g), mode 2 stable split ------------
__global__ __launch_bounds__(256)
void ln_kernel(const float* __restrict__ in, const float* __restrict__ g,
               __half* __restrict__ outh, __half* __restrict__ outl, int mode)
{
    const int row = blockIdx.x;
    const float* xr = in + (size_t)row * DD;
    const int t = threadIdx.x;
    float v[4];
    #pragma unroll
    for (int i = 0; i < 4; i++) v[i] = xr[t + i * 256];
    if (mode == 2) {
        float lm = -FLT_MAX;
        #pragma unroll
        for (int i = 0; i < 4; i++) lm = fmaxf(lm, v[i]);
        float inv = 1.f / blockReduceMax(lm);
        #pragma unroll
        for (int i = 0; i < 4; i++) v[i] *= inv;
    }
    float s = 0.f;
    #pragma unroll
    for (int i = 0; i < 4; i++) s += v[i];
    float mean = blockReduceSum(s) * (1.f / DD);
    float vs = 0.f;
    #pragma unroll
    for (int i = 0; i < 4; i++) { float d = v[i] - mean; vs += d * d; }
    float rstd = rsqrtf(blockReduceSum(vs) * (1.f / DD) + EPSL);
    #pragma unroll
    for (int i = 0; i < 4; i++) {
        int c = t + i * 256;
        float y = (v[i] - mean) * rstd * g[c];
        size_t idx = (size_t)row * DD + c;
        __half h = __float2half_rn(y);
        outh[idx] = h;
        outl[idx] = __float2half_rn(y - __half2float(h));
    }
}

// -------- fused: X = resid + LN(T)*g1 ; split(LN(X)*g2) --------------------
__global__ __launch_bounds__(256)
void ln2_kernel(const float* __restrict__ T, const float* __restrict__ resid,
                const float* __restrict__ g1, const float* __restrict__ g2,
                float* __restrict__ X, __half* __restrict__ outh,
                __half* __restrict__ outl)
{
    const int row = blockIdx.x;
    const int t = threadIdx.x;
    const float* tr = T + (size_t)row * DD;
    const float* rr = resid + (size_t)row * DD;
    float v[4];
    #pragma unroll
    for (int i = 0; i < 4; i++) v[i] = tr[t + i * 256];
    float s = 0.f;
    #pragma unroll
    for (int i = 0; i < 4; i++) s += v[i];
    float mean = blockReduceSum(s) * (1.f / DD);
    float vs = 0.f;
    #pragma unroll
    for (int i = 0; i < 4; i++) { float d = v[i] - mean; vs += d * d; }
    float rstd = rsqrtf(blockReduceSum(vs) * (1.f / DD) + EPSL);
    float x[4];
    #pragma unroll
    for (int i = 0; i < 4; i++) {
        int c = t + i * 256;
        x[i] = rr[(size_t)0 + c] + (v[i] - mean) * rstd * g1[c];
        X[(size_t)row * DD + c] = x[i];
    }
    // second LN on x
    float s2 = 0.f;
    #pragma unroll
    for (int i = 0; i < 4; i++) s2 += x[i];
    float mean2 = blockReduceSum(s2) * (1.f / DD);
    float vs2 = 0.f;
    #pragma unroll
    for (int i = 0; i < 4; i++) { float d = x[i] - mean2; vs2 += d * d; }
    float rstd2 = rsqrtf(blockReduceSum(vs2) * (1.f / DD) + EPSL);
    #pragma unroll
    for (int i = 0; i < 4; i++) {
        int c = t + i * 256;
        float y = (x[i] - mean2) * rstd2 * g2[c];
        size_t idx = (size_t)row * DD + c;
        __half h = __float2half_rn(y);
        outh[idx] = h;
        outl[idx] = __float2half_rn(y - __half2float(h));
    }
}

// ---------------- precompute: rope + rel-pos bias + qkv bias ---------------
__global__ void precompute_kernel(const float* __restrict__ emb,
                                  const float* __restrict__ bkv) {
    int idx = blockIdx.x * blockDim.x + threadIdx.x;
    if (idx < NN * 16) {
        int p = idx >> 4, i = idx & 15;
        float fr = (float)p * powf(10000.f, -(float)(2 * i) / 32.f);
        g_cos[idx] = cosf(fr);
        g_sin[idx] = sinf(fr);
    }
    if (idx < LL * 640) {
        int c = idx % 640;
        g_bqkv[idx] = (c < 512) ? 0.f : bkv[(idx / 640) * 128 + c - 512];
    }
    if (idx >= NN * NKV) return;
    int i = idx / NKV, j = idx % NKV;
    int nn = max(i - j, 0);
    int bucket;
    if (nn < 16) bucket = nn;
    else {
        int vl = 16 + (int)(logf((float)nn * (1.f / 16.f)) / logf(8.f) * 16.f);
        bucket = min(vl, 31);
    }
    #pragma unroll
    for (int h = 0; h < HH; h++)
        g_bias[((size_t)h * NN + i) * NKV + j] = emb[bucket * HH + h];
}

// ---------------- q/kv post ----------------
__global__ __launch_bounds__(256)
void qpost_kernel() {
    int gw   = (blockIdx.x * blockDim.x + threadIdx.x) >> 5;
    int lane = threadIdx.x & 31;
    if (gw >= MM * HH) return;
    int m = gw / HH, h = gw % HH;
    int pos = m % NN;
    float* qp = g_QKV + (size_t)m * 640 + h * 64;
    float q0 = qp[lane], q1 = qp[lane + 32];
    float c = g_cos[pos * 16 + (lane >> 1)];
    float s = g_sin[pos * 16 + (lane >> 1)];
    float part = __shfl_xor_sync(0xffffffffu, q0, 1);
    q0 = (lane & 1) ? fmaf(q0, c, part * s) : fmaf(q0, c, -part * s);
    float inv = 4.f * rsqrtf(warpReduceSum(q0 * q0 + q1 * q1));
    qp[lane] = q0 * inv;
    qp[lane + 32] = q1 * inv;
}
// kv -> Kt (transposed, l2-normed) and V
__global__ __launch_bounds__(256)
void kvpost_kernel(const float* __restrict__ nullkv) {
    int gw   = (blockIdx.x * blockDim.x + threadIdx.x) >> 5;
    int lane = threadIdx.x & 31;
    if (gw >= BB * NKV) return;
    int b = gw / NKV, j = gw % NKV;
    float k0, k1, v0, v1;
    if (j == 0) {
        k0 = nullkv[lane];      k1 = nullkv[lane + 32];
        v0 = nullkv[64 + lane]; v1 = nullkv[96 + lane];
    } else {
        int pos = j - 1;
        const float* kv = g_QKV + ((size_t)(b * NN + pos)) * 640 + 512;
        k0 = kv[lane];      k1 = kv[lane + 32];
        v0 = kv[64 + lane]; v1 = kv[96 + lane];
        float c = g_cos[pos * 16 + (lane >> 1)];
        float s = g_sin[pos * 16 + (lane >> 1)];
        float part = __shfl_xor_sync(0xffffffffu, k0, 1);
        k0 = (lane & 1) ? fmaf(k0, c, part * s) : fmaf(k0, c, -part * s);
    }
    float inv = 4.f * rsqrtf(warpReduceSum(k0 * k0 + k1 * k1));
    g_Kt[((size_t)b * 64 + lane)      * KTP + j] = k0 * inv;
    g_Kt[((size_t)b * 64 + lane + 32) * KTP + j] = k1 * inv;
    size_t o = ((size_t)(b * NKV + j)) * 64;
    g_V[o + lane] = v0;
    g_V[o + lane + 32] = v1;
}

// -------- attention: warp per (b,h,i), lane-per-key blocks of 32 -----------
__global__ __launch_bounds__(256)
void attn_kernel() {
    int gw   = (blockIdx.x * blockDim.x + threadIdx.x) >> 5;
    int lane = threadIdx.x & 31;
    if (gw >= BB * HH * NN) return;
    int i  = gw % NN;
    int bh = gw / NN;
    int h  = bh % HH, b = bh / HH;

    const float* qp = g_QKV + ((size_t)(b * NN + i)) * 640 + h * 64;
    float q0 = qp[lane], q1 = qp[lane + 32];
    const float* Ktb = g_Kt + (size_t)b * 64 * KTP;
    const float* Vb  = g_V  + (size_t)b * NKV * 64;
    const float* bp  = g_bias + ((size_t)h * NN + i) * NKV;

    float m = -1e30f, lsum = 0.f, o0 = 0.f, o1 = 0.f;
    const int jmax = i + 1;
    for (int j0 = 0; j0 <= jmax; j0 += 32) {
        const int j = j0 + lane;
        // score: bias + q . Kt[:, j]
        float a0 = 0.f, a1 = 0.f, a2 = 0.f, a3 = 0.f;
        #pragma unroll
        for (int d = 0; d < 32; d += 4) {
            a0 = fmaf(__shfl_sync(0xffffffffu, q0, d    ), Ktb[(d    ) * KTP + j], a0);
            a1 = fmaf(__shfl_sync(0xffffffffu, q0, d + 1), Ktb[(d + 1) * KTP + j], a1);
            a2 = fmaf(__shfl_sync(0xffffffffu, q0, d + 2), Ktb[(d + 2) * KTP + j], a2);
            a3 = fmaf(__shfl_sync(0xffffffffu, q0, d + 3), Ktb[(d + 3) * KTP + j], a3);
        }
        #pragma unroll
        for (int d = 0; d < 32; d += 4) {
            a0 = fmaf(__shfl_sync(0xffffffffu, q1, d    ), Ktb[(d + 32) * KTP + j], a0);
            a1 = fmaf(__shfl_sync(0xffffffffu, q1, d + 1), Ktb[(d + 33) * KTP + j], a1);
            a2 = fmaf(__shfl_sync(0xffffffffu, q1, d + 2), Ktb[(d + 34) * KTP + j], a2);
            a3 = fmaf(__shfl_sync(0xffffffffu, q1, d + 3), Ktb[(d + 35) * KTP + j], a3);
        }
        float s = bp[j] + ((a0 + a1) + (a2 + a3));
        if (j > jmax) s = -1e30f;
        // block max + online-softmax update
        float mb = s;
        #pragma unroll
        for (int o = 16; o > 0; o >>= 1) mb = fmaxf(mb, __shfl_xor_sync(0xffffffffu, mb, o));
        float mn = fmaxf(m, mb);
        float corr = __expf(m - mn);
        float w = __expf(s - mn);
        float ws = w;
        #pragma unroll
        for (int o = 16; o > 0; o >>= 1) ws += __shfl_xor_sync(0xffffffffu, ws, o);
        lsum = lsum * corr + ws;
        o0 *= corr; o1 *= corr;
        const float* vrow = Vb + (size_t)j0 * 64;
        #pragma unroll
        for (int l2 = 0; l2 < 32; l2++) {
            float wl = __shfl_sync(0xffffffffu, w, l2);
            o0 = fmaf(wl, vrow[l2 * 64 + lane],      o0);
            o1 = fmaf(wl, vrow[l2 * 64 + lane + 32], o1);
        }
        m = mn;
    }
    float inv = 1.f / lsum;
    o0 *= inv; o1 *= inv;
    size_t op = ((size_t)(b * NN + i)) * 512 + h * 64;
    __half h0 = __float2half_rn(o0);
    __half h1 = __float2half_rn(o1);
    g_Oh[op + lane]      = h0;  g_Ol[op + lane]      = __float2half_rn(o0 - __half2float(h0));
    g_Oh[op + lane + 32] = h1;  g_Ol[op + lane + 32] = __float2half_rn(o1 - __half2float(h1));
}

// ---------------- host orchestration --------------------------------------
static inline void run_gemm(const __half* Ah, const __half* Al, const __half* Bh,
                            const float* bias, float* C,
                            __half* outh, __half* outl,
                            int M, int N, int K, int mode) {
    dim3 grid(N / 128, (M + 127) / 128);
    bgemm_kernel<<<grid, 256, SMEM_TOT>>>(Ah, Al, Bh, bias, C, outh, outl, M, N, K, mode);
}

extern "C" void kernel_launch(void* const* d_in, const int* in_sizes, int n_in,
                              void* d_out, int out_size) {
    (void)in_sizes; (void)n_in; (void)out_size;
    const float* x            = (const float*)d_in[0];
    const float* attn_norm_g  = (const float*)d_in[1];
    const float* Wq           = (const float*)d_in[2];
    const float* Wkv          = (const float*)d_in[3];
    const float* bkv          = (const float*)d_in[4];
    const float* null_kv      = (const float*)d_in[5];
    const float* Wo           = (const float*)d_in[6];
    const float* out_norm_g   = (const float*)d_in[7];
    const float* ff_norm_g    = (const float*)d_in[8];
    const float* Wff1         = (const float*)d_in[9];
    const float* Wff2         = (const float*)d_in[10];
    const float* relpos       = (const float*)d_in[11];
    const float* final_norm_g = (const float*)d_in[12];
    const float* Wproj        = (const float*)d_in[13];
    float* out = (float*)d_out;

    cudaFuncSetAttribute(bgemm_kernel, cudaFuncAttributeMaxDynamicSharedMemorySize, SMEM_TOT);

    float *X, *QKV, *T, *BQKV;
    __half *XNh, *XNl, *Oh, *Ol, *AGh, *AGl;
    __half *WqkvT, *WoT, *W1T, *W2T, *WpT;
    cudaGetSymbolAddress((void**)&X,   g_X);
    cudaGetSymbolAddress((void**)&QKV, g_QKV);
    cudaGetSymbolAddress((void**)&T,   g_T);
    cudaGetSymbolAddress((void**)&BQKV, g_bqkv);
    cudaGetSymbolAddress((void**)&XNh, g_XNh); cudaGetSymbolAddress((void**)&XNl, g_XNl);
    cudaGetSymbolAddress((void**)&Oh,  g_Oh);  cudaGetSymbolAddress((void**)&Ol,  g_Ol);
    cudaGetSymbolAddress((void**)&AGh, g_AGh); cudaGetSymbolAddress((void**)&AGl, g_AGl);
    cudaGetSymbolAddress((void**)&WqkvT, g_WqkvT);
    cudaGetSymbolAddress((void**)&WoT, g_WoT);
    cudaGetSymbolAddress((void**)&W1T, g_Wff1T);
    cudaGetSymbolAddress((void**)&W2T, g_Wff2T);
    cudaGetSymbolAddress((void**)&WpT, g_WprojT);

    // launch 1: precompute
    precompute_kernel<<<(NN * NKV + 255) / 256, 256>>>(relpos, bkv);

    // launch 2: fused weight transpose
    WTable tab;
    int di = 0;
    for (int l = 0; l < LL; l++) {
        tab.d[di++] = { Wq   + (size_t)l * DD * 512,     WqkvT + (size_t)l * 640 * DD,            DD,  512,     0 };
        tab.d[di++] = { Wkv  + (size_t)l * DD * 128,     WqkvT + (size_t)l * 640 * DD + 512 * DD, DD,  128,     0 };
        tab.d[di++] = { Wo   + (size_t)l * 512 * DD,     WoT + (size_t)l * DD * 512,              512, DD,      0 };
        tab.d[di++] = { Wff1 + (size_t)l * DD * 2 * FFD, W1T + (size_t)l * 2 * FFD * DD,          DD,  2 * FFD, 1 };
        tab.d[di++] = { Wff2 + (size_t)l * FFD * DD,     W2T + (size_t)l * DD * FFD,              FFD, DD,      0 };
    }
    tab.d[di++] = { Wproj, WpT, DD, DD, 0 };
    tab.off[0] = 0;
    for (int i = 0; i < 21; i++)
        tab.off[i + 1] = tab.off[i] + (tab.d[i].N >> 5) * (tab.d[i].K >> 5);
    wsplit_all_kernel<<<tab.off[21], dim3(32, 8)>>>(tab);

    for (int l = 0; l < LL; l++) {
        if (l == 0) {
            // launch 3: first attn LN (reads harness input directly)
            ln_kernel<<<MM, 256>>>(x, attn_norm_g, XNh, XNl, 0);
        }
        // launch 4 (l=0): merged QKV gemm  <- ncu capture slot
        run_gemm(XNh, XNl, WqkvT + (size_t)l * 640 * DD, BQKV + l * 640,
                 QKV, nullptr, nullptr, MM, 640, DD, 0);
        qpost_kernel<<<(MM * HH * 32 + 255) / 256, 256>>>();
        kvpost_kernel<<<(BB * NKV * 32 + 255) / 256, 256>>>(null_kv + (size_t)l * 128);
        attn_kernel<<<(BB * HH * NN * 32 + 255) / 256, 256>>>();
        run_gemm(Oh, Ol, WoT + (size_t)l * DD * 512, nullptr, T, nullptr, nullptr, MM, DD, 512, 0);
        // fused: X = resid + LN(T)*g_out ; XN = split(LN(X)*g_ff)
        ln2_kernel<<<MM, 256>>>(T, (l == 0) ? x : X, out_norm_g + (size_t)l * DD,
                                ff_norm_g + (size_t)l * DD, X, XNh, XNl);
        run_gemm(XNh, XNl, W1T + (size_t)l * 2 * FFD * DD, nullptr, nullptr, AGh, AGl, MM, 2 * FFD, DD, 2);
        run_gemm(AGh, AGl, W2T + (size_t)l * DD * FFD, nullptr, X, nullptr, nullptr, MM, DD, FFD, 1);
        if (l + 1 < LL) {
            ln_kernel<<<MM, 256>>>(X, attn_norm_g + (size_t)(l + 1) * DD, XNh, XNl, 0);
        }
    }

    ln_kernel<<<MM, 256>>>(X, final_norm_g, XNh, XNl, 2);
    run_gemm(XNh, XNl, WpT, nullptr, out, nullptr, nullptr, MM, DD, DD, 0);
}